// round 6
// baseline (speedup 1.0000x reference)
#include <cuda_runtime.h>
#include <cuda_bf16.h>
#include <cstdint>

#define N_NODES 100000
#define N_GRAPHS 64
#define HID 64
#define MAX_E 1600000
#define NSCAN_BLK 98   // ceil(100000/1024)

// ---------------- scratch (static device globals; no runtime alloc) --------
__device__ int   g_deg[N_NODES];
__device__ int   g_rowptr[N_NODES + 1];
__device__ int   g_tmp[N_NODES];
__device__ int   g_col[MAX_E];
__device__ float g_y[N_NODES * HID];
__device__ float g_r[N_NODES * HID];
__device__ float g_h[N_NODES * HID];
__device__ int   g_bsum[256];
__device__ int   g_boff[256];
__device__ float g_pool[N_GRAPHS * HID];
__device__ float g_cnt[N_GRAPHS];
__device__ int   g_flags[2];

// ---------------- dtype detection ------------------------------------------
__global__ void k_detect(const int* __restrict__ edge, const int* __restrict__ batch) {
    __shared__ int s_nz;
    int t = threadIdx.x;
    if (t == 0) s_nz = 0;
    __syncthreads();
    int v;
    if (blockIdx.x == 0) v = edge[2 * t + 1];
    else                 v = batch[2 * (30000 + t * 64) + 1];
    if (v != 0) atomicOr(&s_nz, 1);
    __syncthreads();
    if (t == 0) g_flags[blockIdx.x] = (s_nz == 0) ? 1 : 0;
}

// ---------------- CSR build -------------------------------------------------
__global__ void k_zero_deg() {
    int i = blockIdx.x * blockDim.x + threadIdx.x;
    if (i < N_NODES) g_deg[i] = 0;
}
__global__ void k_hist(const int* __restrict__ edge, int E) {
    int f = g_flags[0];
    int stride = gridDim.x * blockDim.x;
    for (int e = blockIdx.x * blockDim.x + threadIdx.x; e < E; e += stride) {
        int d = f ? edge[2 * (E + e)] : edge[E + e];
        atomicAdd(&g_deg[d], 1);
    }
}
__global__ void k_scan1() {
    __shared__ int sm[1024];
    int i = blockIdx.x * 1024 + threadIdx.x;
    int v = (i < N_NODES) ? g_deg[i] : 0;
    sm[threadIdx.x] = v;
    __syncthreads();
    for (int off = 1; off < 1024; off <<= 1) {
        int u = (threadIdx.x >= off) ? sm[threadIdx.x - off] : 0;
        __syncthreads();
        sm[threadIdx.x] += u;
        __syncthreads();
    }
    if (i < N_NODES) g_tmp[i] = sm[threadIdx.x];
    if (threadIdx.x == 1023) g_bsum[blockIdx.x] = sm[1023];
}
__global__ void k_scan2(int nb, int E) {
    __shared__ int sm[128];
    int t = threadIdx.x;
    int v = (t < nb) ? g_bsum[t] : 0;
    sm[t] = v;
    __syncthreads();
    for (int off = 1; off < 128; off <<= 1) {
        int u = (t >= off) ? sm[t - off] : 0;
        __syncthreads();
        sm[t] += u;
        __syncthreads();
    }
    if (t < nb) g_boff[t] = sm[t] - v;
    if (t == 0) { g_rowptr[0] = 0; g_rowptr[N_NODES] = E; }
}
__global__ void k_scan3() {
    int i = blockIdx.x * 1024 + threadIdx.x;
    if (i < N_NODES) g_rowptr[i + 1] = g_tmp[i] + g_boff[blockIdx.x];
}
__global__ void k_cursor() {
    int i = blockIdx.x * blockDim.x + threadIdx.x;
    if (i < N_NODES) g_tmp[i] = g_rowptr[i];
}
__global__ void k_scatter(const int* __restrict__ edge, int E) {
    int f = g_flags[0];
    int stride = gridDim.x * blockDim.x;
    for (int e = blockIdx.x * blockDim.x + threadIdx.x; e < E; e += stride) {
        int s = f ? edge[2 * e] : edge[e];
        int d = f ? edge[2 * (E + e)] : edge[E + e];
        int pos = atomicAdd(&g_tmp[d], 1);
        g_col[pos] = s;
    }
}

// ================= HMMA helpers (plain sm_80+ PTX; no 'a' features) ========
__device__ __forceinline__ uint32_t smem_u32(const void* p) {
    uint32_t a;
    asm("{ .reg .u64 t; cvta.to.shared.u64 t, %1; cvt.u32.u64 %0, t; }" : "=r"(a) : "l"(p));
    return a;
}
__device__ __forceinline__ void ldmx4(uint32_t& r0, uint32_t& r1, uint32_t& r2, uint32_t& r3,
                                      uint32_t addr) {
    asm volatile("ldmatrix.sync.aligned.m8n8.x4.shared.b16 {%0,%1,%2,%3}, [%4];"
                 : "=r"(r0), "=r"(r1), "=r"(r2), "=r"(r3) : "r"(addr));
}
__device__ __forceinline__ void mma16816(float* c, const uint32_t* a, uint32_t b0, uint32_t b1) {
    asm volatile("mma.sync.aligned.m16n8k16.row.col.f32.bf16.bf16.f32 "
                 "{%0,%1,%2,%3}, {%4,%5,%6,%7}, {%8,%9}, {%0,%1,%2,%3};"
                 : "+f"(c[0]), "+f"(c[1]), "+f"(c[2]), "+f"(c[3])
                 : "r"(a[0]), "r"(a[1]), "r"(a[2]), "r"(a[3]), "r"(b0), "r"(b1));
}
__device__ __forceinline__ uint32_t pack_hi(float x, float y, uint32_t& lo) {
    __nv_bfloat16 hx = __float2bfloat16(x);
    __nv_bfloat16 hy = __float2bfloat16(y);
    __nv_bfloat16 lx = __float2bfloat16(x - __bfloat162float(hx));
    __nv_bfloat16 ly = __float2bfloat16(y - __bfloat162float(hy));
    __nv_bfloat162 l2 = make_bfloat162(lx, ly);
    __nv_bfloat162 h2 = make_bfloat162(hx, hy);
    lo = *(uint32_t*)&l2;
    return *(uint32_t*)&h2;
}

// =============== tensor-core fused GEMM: y = A@Wrel ; r = A@Wroot + b =======
// Split-bf16, acc = AhBh + AhBl + AlBh in fp32 (mma.sync m16n8k16).
// Block tile: 64 rows x 128 out-cols. 256 threads = 8 warps (2m x 4n),
// warp tile 32 x 32.
template <int KD>
__global__ __launch_bounds__(256) void k_hgemm(const float* __restrict__ A,
                                               const float* __restrict__ Wrel,
                                               const float* __restrict__ Wroot,
                                               const float* __restrict__ bias) {
    extern __shared__ char smem[];
    constexpr int SA = KD + 8;                       // padded row stride (bf16 elems)
    constexpr int ABYTES = 64 * SA * 2;
    constexpr int BBYTES = 128 * SA * 2;
    char* a_hi = smem;
    char* a_lo = smem + ABYTES;
    char* b_hi = smem + 2 * ABYTES;
    char* b_lo = smem + 2 * ABYTES + BBYTES;
    float* bsh = (float*)(smem + 2 * ABYTES + 2 * BBYTES);

    const int t = threadIdx.x;
    const int wid = t >> 5;
    const int lane = t & 31;
    const int row0 = blockIdx.x * 64;

    if (t < 64) bsh[t] = bias[t];

    // ---- A tile: 64 x KD fp32 -> split bf16 (row-major, padded) ----
    {
        constexpr int G = 64 * KD / 4;
        for (int g = t; g < G; g += 256) {
            int row = g / (KD / 4);
            int k4 = (g % (KD / 4)) * 4;
            float4 v = make_float4(0.f, 0.f, 0.f, 0.f);
            if (row0 + row < N_NODES)
                v = *(const float4*)(A + (size_t)(row0 + row) * KD + k4);
            uint32_t l01, l23;
            uint32_t h01 = pack_hi(v.x, v.y, l01);
            uint32_t h23 = pack_hi(v.z, v.w, l23);
            uint32_t off = (uint32_t)(row * SA + k4) * 2;
            *(uint2*)(a_hi + off) = make_uint2(h01, h23);
            *(uint2*)(a_lo + off) = make_uint2(l01, l23);
        }
    }
    // ---- B tile: B[n][k] = W[k][n] (n-major, padded) ----
    {
        constexpr int G = 128 * KD / 4;
        for (int g = t; g < G; g += 256) {
            int n = g / (KD / 4);
            int k4 = (g % (KD / 4)) * 4;
            const float* src = (n < 64) ? (Wrel + n) : (Wroot + (n - 64));
            float v0 = src[(k4 + 0) * 64];
            float v1 = src[(k4 + 1) * 64];
            float v2 = src[(k4 + 2) * 64];
            float v3 = src[(k4 + 3) * 64];
            uint32_t l01, l23;
            uint32_t h01 = pack_hi(v0, v1, l01);
            uint32_t h23 = pack_hi(v2, v3, l23);
            uint32_t off = (uint32_t)(n * SA + k4) * 2;
            *(uint2*)(b_hi + off) = make_uint2(h01, h23);
            *(uint2*)(b_lo + off) = make_uint2(l01, l23);
        }
    }
    __syncthreads();

    // warp tile: rows m_base..m_base+31, cols n_base..n_base+31
    const int m_base = (wid & 1) * 32;
    const int n_base = (wid >> 1) * 32;

    float c[8][4];   // frag f = mi*4+ni : rows m_base+mi*16, cols n_base+ni*8
#pragma unroll
    for (int f = 0; f < 8; f++)
#pragma unroll
        for (int i = 0; i < 4; i++) c[f][i] = 0.f;

    const uint32_t sa_hi = smem_u32(a_hi), sa_lo = smem_u32(a_lo);
    const uint32_t sb_hi = smem_u32(b_hi), sb_lo = smem_u32(b_lo);

    // lane-derived ldmatrix row/col selectors
    const int a_row = (lane & 15);            // + m_base + mi*16
    const int a_kof = (lane >> 4) * 8;        // + ks
    const int b_row = ((lane >> 4) & 1) * 8 + (lane & 7);  // + n_base + nj*16
    const int b_kof = ((lane >> 3) & 1) * 8;  // + ks

#pragma unroll
    for (int ks = 0; ks < KD; ks += 16) {
        uint32_t ah[2][4], al[2][4];
#pragma unroll
        for (int mi = 0; mi < 2; mi++) {
            uint32_t off = (uint32_t)((m_base + mi * 16 + a_row) * SA + ks + a_kof) * 2;
            ldmx4(ah[mi][0], ah[mi][1], ah[mi][2], ah[mi][3], sa_hi + off);
            ldmx4(al[mi][0], al[mi][1], al[mi][2], al[mi][3], sa_lo + off);
        }
        uint32_t bh[4][2], bl[4][2];
#pragma unroll
        for (int nj = 0; nj < 2; nj++) {
            uint32_t off = (uint32_t)((n_base + nj * 16 + b_row) * SA + ks + b_kof) * 2;
            uint32_t r0, r1, r2, r3;
            ldmx4(r0, r1, r2, r3, sb_hi + off);
            bh[nj * 2][0] = r0; bh[nj * 2][1] = r1;
            bh[nj * 2 + 1][0] = r2; bh[nj * 2 + 1][1] = r3;
            ldmx4(r0, r1, r2, r3, sb_lo + off);
            bl[nj * 2][0] = r0; bl[nj * 2][1] = r1;
            bl[nj * 2 + 1][0] = r2; bl[nj * 2 + 1][1] = r3;
        }
#pragma unroll
        for (int mi = 0; mi < 2; mi++)
#pragma unroll
            for (int ni = 0; ni < 4; ni++) {
                float* cf = c[mi * 4 + ni];
                mma16816(cf, ah[mi], bh[ni][0], bh[ni][1]);   // Ah*Bh
                mma16816(cf, ah[mi], bl[ni][0], bl[ni][1]);   // Ah*Bl
                mma16816(cf, al[mi], bh[ni][0], bh[ni][1]);   // Al*Bh
            }
    }

    // ---- epilogue ----
    const int er = lane >> 2;          // row within 8-row group
    const int ec = (lane & 3) * 2;     // col pair
#pragma unroll
    for (int mi = 0; mi < 2; mi++) {
#pragma unroll
        for (int half = 0; half < 2; half++) {
            int m = m_base + mi * 16 + half * 8 + er;
            int node = row0 + m;
            if (node >= N_NODES) continue;
#pragma unroll
            for (int ni = 0; ni < 4; ni++) {
                int j = n_base + ni * 8 + ec;
                float v0 = c[mi * 4 + ni][half * 2 + 0];
                float v1 = c[mi * 4 + ni][half * 2 + 1];
                if (j < 64) {
                    *(float2*)(g_y + (size_t)node * 64 + j) = make_float2(v0, v1);
                } else {
                    *(float2*)(g_r + (size_t)node * 64 + (j - 64)) =
                        make_float2(v0 + bsh[j - 64], v1 + bsh[j - 63]);
                }
            }
        }
    }
}

// ---------------- aggregation: h = relu(sum_{s->i} y[s] + r[i]) -------------
__global__ void k_agg() {
    int w = (blockIdx.x * blockDim.x + threadIdx.x) >> 5;
    int lane = threadIdx.x & 31;
    if (w >= N_NODES) return;
    int beg = g_rowptr[w];
    int end = g_rowptr[w + 1];
    const float2* y2 = (const float2*)g_y;
    float2 a0 = make_float2(0.f, 0.f), a1 = make_float2(0.f, 0.f);
    int e = beg;
    for (; e + 1 < end; e += 2) {
        int s0 = __ldg(&g_col[e]);
        int s1 = __ldg(&g_col[e + 1]);
        float2 v0 = __ldg(&y2[(size_t)s0 * 32 + lane]);
        float2 v1 = __ldg(&y2[(size_t)s1 * 32 + lane]);
        a0.x += v0.x; a0.y += v0.y;
        a1.x += v1.x; a1.y += v1.y;
    }
    if (e < end) {
        int s = __ldg(&g_col[e]);
        float2 v = __ldg(&y2[(size_t)s * 32 + lane]);
        a0.x += v.x; a0.y += v.y;
    }
    float2 rv = ((const float2*)g_r)[(size_t)w * 32 + lane];
    float2 o;
    o.x = fmaxf(a0.x + a1.x + rv.x, 0.f);
    o.y = fmaxf(a0.y + a1.y + rv.y, 0.f);
    ((float2*)g_h)[(size_t)w * 32 + lane] = o;
}

// ---------------- pooling ---------------------------------------------------
__global__ void k_zero_pool() {
    int i = blockIdx.x * blockDim.x + threadIdx.x;
    if (i < N_GRAPHS * HID) g_pool[i] = 0.f;
    if (i < N_GRAPHS) g_cnt[i] = 0.f;
}
__global__ void k_pool(const int* __restrict__ batch) {
    int chunk = (blockIdx.x * blockDim.x + threadIdx.x) >> 5;
    int lane = threadIdx.x & 31;
    int n0 = chunk * 32;
    if (n0 >= N_NODES) return;
    int n1 = min(n0 + 32, N_NODES);
    int f = g_flags[1];
    const float2* h2 = (const float2*)g_h;
    float2 acc = make_float2(0.f, 0.f);
    int cnt = 0;
    int cur = f ? batch[2 * n0] : batch[n0];
    for (int n = n0; n < n1; n++) {
        int g = f ? batch[2 * n] : batch[n];
        if (g != cur) {
            atomicAdd(&g_pool[cur * 64 + 2 * lane], acc.x);
            atomicAdd(&g_pool[cur * 64 + 2 * lane + 1], acc.y);
            if (lane == 0) atomicAdd(&g_cnt[cur], (float)cnt);
            acc = make_float2(0.f, 0.f); cnt = 0; cur = g;
        }
        float2 v = h2[(size_t)n * 32 + lane];
        acc.x += v.x; acc.y += v.y; cnt++;
    }
    atomicAdd(&g_pool[cur * 64 + 2 * lane], acc.x);
    atomicAdd(&g_pool[cur * 64 + 2 * lane + 1], acc.y);
    if (lane == 0) atomicAdd(&g_cnt[cur], (float)cnt);
}

// ---------------- head ------------------------------------------------------
__global__ void k_head(const float* __restrict__ w1, const float* __restrict__ b1,
                       const float* __restrict__ w2, const float* __restrict__ b2,
                       float* __restrict__ out) {
    __shared__ float s_w1[64 * 64], s_b1[64], s_w2[128], s_b2[2];
    int t = threadIdx.x;
    for (int i = t; i < 64 * 64; i += 64) s_w1[i] = w1[i];
    s_b1[t] = b1[t];
    for (int i = t; i < 128; i += 64) s_w2[i] = w2[i];
    if (t < 2) s_b2[t] = b2[t];
    __syncthreads();

    float cnt = fmaxf(g_cnt[t], 1.f);
    float m[64];
#pragma unroll
    for (int c = 0; c < 64; c++) m[c] = g_pool[t * 64 + c] / cnt;

    float o0 = s_b2[0], o1 = s_b2[1];
    for (int j = 0; j < 64; j++) {
        float z = s_b1[j];
#pragma unroll 8
        for (int k = 0; k < 64; k++) z += m[k] * s_w1[k * 64 + j];
        z = fmaxf(z, 0.f);
        o0 += z * s_w2[j * 2];
        o1 += z * s_w2[j * 2 + 1];
    }
    out[t * 2 + 0] = o0;
    out[t * 2 + 1] = o1;
}

// ---------------- launch ----------------------------------------------------
extern "C" void kernel_launch(void* const* d_in, const int* in_sizes, int n_in,
                              void* d_out, int out_size) {
    const float* x       = (const float*)d_in[0];
    const int*   edge    = (const int*)d_in[1];
    const int*   batch   = (const int*)d_in[2];
    const float* w_rel0  = (const float*)d_in[3];
    const float* b_rel0  = (const float*)d_in[4];
    const float* w_root0 = (const float*)d_in[5];
    const float* w_rel1  = (const float*)d_in[6];
    const float* b_rel1  = (const float*)d_in[7];
    const float* w_root1 = (const float*)d_in[8];
    const float* w_rel2  = (const float*)d_in[9];
    const float* b_rel2  = (const float*)d_in[10];
    const float* w_root2 = (const float*)d_in[11];
    const float* head_w1 = (const float*)d_in[12];
    const float* head_b1 = (const float*)d_in[13];
    const float* head_w2 = (const float*)d_in[14];
    const float* head_b2 = (const float*)d_in[15];
    float* out = (float*)d_out;

    const int E = in_sizes[1] / 2;

    // smem sizes: 2*A + 2*B + bias
    const int smem128 = 2 * (64 * (128 + 8) * 2) + 2 * (128 * (128 + 8) * 2) + 256;
    const int smem64  = 2 * (64 * (64 + 8) * 2) + 2 * (128 * (64 + 8) * 2) + 256;
    cudaFuncSetAttribute(k_hgemm<128>, cudaFuncAttributeMaxDynamicSharedMemorySize, smem128);
    cudaFuncSetAttribute(k_hgemm<64>,  cudaFuncAttributeMaxDynamicSharedMemorySize, smem64);

    void* hptr = nullptr;
    cudaGetSymbolAddress(&hptr, g_h);
    const float* h = (const float*)hptr;

    const int gblk = (N_NODES + 63) / 64;   // 1563
    const int ablk = (N_NODES + 7) / 8;

    // layer-0 GEMM is independent of the CSR build — launch it first
    k_hgemm<128><<<gblk, 256, smem128>>>(x, w_rel0, w_root0, b_rel0);

    // CSR build
    k_detect<<<2, 256>>>(edge, batch);
    k_zero_deg<<<(N_NODES + 255) / 256, 256>>>();
    k_hist<<<1024, 256>>>(edge, E);
    k_scan1<<<NSCAN_BLK, 1024>>>();
    k_scan2<<<1, 128>>>(NSCAN_BLK, E);
    k_scan3<<<NSCAN_BLK, 1024>>>();
    k_cursor<<<(N_NODES + 1023) / 1024, 1024>>>();
    k_scatter<<<1024, 256>>>(edge, E);

    // layer 0 aggregate, then layers 1 & 2
    k_agg<<<ablk, 256>>>();
    k_hgemm<64><<<gblk, 256, smem64>>>(h, w_rel1, w_root1, b_rel1);
    k_agg<<<ablk, 256>>>();
    k_hgemm<64><<<gblk, 256, smem64>>>(h, w_rel2, w_root2, b_rel2);
    k_agg<<<ablk, 256>>>();

    // pooling + head
    k_zero_pool<<<(N_GRAPHS * HID + 255) / 256, 256>>>();
    k_pool<<<(N_NODES / 32 * 32 + 255) / 256, 256>>>(batch);
    k_head<<<1, 64>>>(head_w1, head_b1, head_w2, head_b2, out);
}

// round 8
// speedup vs baseline: 1.4035x; 1.4035x over previous
#include <cuda_runtime.h>
#include <cuda_bf16.h>
#include <cstdint>

#define N_NODES 100000
#define N_GRAPHS 64
#define HID 64
#define MAX_E 1600000
#define NSCAN_BLK 98   // ceil(100000/1024)

// ---------------- scratch (static device globals; no runtime alloc) --------
__device__ int   g_deg[N_NODES];
__device__ int   g_rowptr[N_NODES + 1];
__device__ int   g_tmp[N_NODES];
__device__ int   g_col[MAX_E];
__device__ float g_y[N_NODES * HID];
__device__ float g_r[N_NODES * HID];
__device__ float g_h[N_NODES * HID];
__device__ uint32_t g_hh[N_NODES * HID / 2];   // h split-bf16 hi (bf16x2 packed)
__device__ uint32_t g_hl[N_NODES * HID / 2];   // h split-bf16 lo
__device__ uint16_t g_bh0[128 * 128], g_bl0[128 * 128];
__device__ uint16_t g_bh1[128 * 64],  g_bl1[128 * 64];
__device__ uint16_t g_bh2[128 * 64],  g_bl2[128 * 64];
__device__ int   g_bsum[256];
__device__ int   g_boff[256];
__device__ float g_pool[N_GRAPHS * HID];
__device__ float g_cnt[N_GRAPHS];
__device__ int   g_flags[2];

// ---------------- dtype detection ------------------------------------------
__global__ void k_detect(const int* __restrict__ edge, const int* __restrict__ batch) {
    __shared__ int s_nz;
    int t = threadIdx.x;
    if (t == 0) s_nz = 0;
    __syncthreads();
    int v;
    if (blockIdx.x == 0) v = edge[2 * t + 1];
    else                 v = batch[2 * (30000 + t * 64) + 1];
    if (v != 0) atomicOr(&s_nz, 1);
    __syncthreads();
    if (t == 0) g_flags[blockIdx.x] = (s_nz == 0) ? 1 : 0;
}

// ---------------- CSR build -------------------------------------------------
__global__ void k_zero_deg() {
    int i = blockIdx.x * blockDim.x + threadIdx.x;
    if (i < N_NODES) g_deg[i] = 0;
}
__global__ void k_hist(const int* __restrict__ edge, int E) {
    int f = g_flags[0];
    int stride = gridDim.x * blockDim.x;
    for (int e = blockIdx.x * blockDim.x + threadIdx.x; e < E; e += stride) {
        int d = f ? edge[2 * (E + e)] : edge[E + e];
        atomicAdd(&g_deg[d], 1);
    }
}
__global__ void k_scan1() {
    __shared__ int sm[1024];
    int i = blockIdx.x * 1024 + threadIdx.x;
    int v = (i < N_NODES) ? g_deg[i] : 0;
    sm[threadIdx.x] = v;
    __syncthreads();
    for (int off = 1; off < 1024; off <<= 1) {
        int u = (threadIdx.x >= off) ? sm[threadIdx.x - off] : 0;
        __syncthreads();
        sm[threadIdx.x] += u;
        __syncthreads();
    }
    if (i < N_NODES) g_tmp[i] = sm[threadIdx.x];
    if (threadIdx.x == 1023) g_bsum[blockIdx.x] = sm[1023];
}
__global__ void k_scan2(int nb, int E) {
    __shared__ int sm[128];
    int t = threadIdx.x;
    int v = (t < nb) ? g_bsum[t] : 0;
    sm[t] = v;
    __syncthreads();
    for (int off = 1; off < 128; off <<= 1) {
        int u = (t >= off) ? sm[t - off] : 0;
        __syncthreads();
        sm[t] += u;
        __syncthreads();
    }
    if (t < nb) g_boff[t] = sm[t] - v;
    if (t == 0) { g_rowptr[0] = 0; g_rowptr[N_NODES] = E; }
}
__global__ void k_scan3() {
    int i = blockIdx.x * 1024 + threadIdx.x;
    if (i < N_NODES) g_rowptr[i + 1] = g_tmp[i] + g_boff[blockIdx.x];
}
__global__ void k_cursor() {
    int i = blockIdx.x * blockDim.x + threadIdx.x;
    if (i < N_NODES) g_tmp[i] = g_rowptr[i];
}
__global__ void k_scatter(const int* __restrict__ edge, int E) {
    int f = g_flags[0];
    int stride = gridDim.x * blockDim.x;
    for (int e = blockIdx.x * blockDim.x + threadIdx.x; e < E; e += stride) {
        int s = f ? edge[2 * e] : edge[e];
        int d = f ? edge[2 * (E + e)] : edge[E + e];
        int pos = atomicAdd(&g_tmp[d], 1);
        g_col[pos] = s;
    }
}

// ================= HMMA helpers (plain sm_80+ PTX) =========================
__device__ __forceinline__ uint32_t smem_u32(const void* p) {
    uint32_t a;
    asm("{ .reg .u64 t; cvta.to.shared.u64 t, %1; cvt.u32.u64 %0, t; }" : "=r"(a) : "l"(p));
    return a;
}
__device__ __forceinline__ void ldmx4(uint32_t& r0, uint32_t& r1, uint32_t& r2, uint32_t& r3,
                                      uint32_t addr) {
    asm volatile("ldmatrix.sync.aligned.m8n8.x4.shared.b16 {%0,%1,%2,%3}, [%4];"
                 : "=r"(r0), "=r"(r1), "=r"(r2), "=r"(r3) : "r"(addr));
}
__device__ __forceinline__ void mma16816(float* c, const uint32_t* a, uint32_t b0, uint32_t b1) {
    asm volatile("mma.sync.aligned.m16n8k16.row.col.f32.bf16.bf16.f32 "
                 "{%0,%1,%2,%3}, {%4,%5,%6,%7}, {%8,%9}, {%0,%1,%2,%3};"
                 : "+f"(c[0]), "+f"(c[1]), "+f"(c[2]), "+f"(c[3])
                 : "r"(a[0]), "r"(a[1]), "r"(a[2]), "r"(a[3]), "r"(b0), "r"(b1));
}
__device__ __forceinline__ uint32_t pack_hi(float x, float y, uint32_t& lo) {
    __nv_bfloat16 hx = __float2bfloat16(x);
    __nv_bfloat16 hy = __float2bfloat16(y);
    __nv_bfloat16 lx = __float2bfloat16(x - __bfloat162float(hx));
    __nv_bfloat16 ly = __float2bfloat16(y - __bfloat162float(hy));
    __nv_bfloat162 l2 = make_bfloat162(lx, ly);
    __nv_bfloat162 h2 = make_bfloat162(hx, hy);
    lo = *(uint32_t*)&l2;
    return *(uint32_t*)&h2;
}

// ---------------- one-time weight split: W -> Bh/Bl [128][KD] bf16 ----------
__global__ void k_bsplit(const float* __restrict__ Wrel, const float* __restrict__ Wroot,
                         uint16_t* __restrict__ bh, uint16_t* __restrict__ bl, int KD) {
    int idx = blockIdx.x * blockDim.x + threadIdx.x;   // idx = k*128 + n (coalesced read)
    if (idx >= 128 * KD) return;
    int k = idx >> 7, n = idx & 127;
    float v = (n < 64) ? Wrel[k * 64 + n] : Wroot[k * 64 + (n - 64)];
    __nv_bfloat16 h = __float2bfloat16(v);
    __nv_bfloat16 l = __float2bfloat16(v - __bfloat162float(h));
    bh[n * KD + k] = *(uint16_t*)&h;
    bl[n * KD + k] = *(uint16_t*)&l;
}

// =============== tensor-core fused GEMM: y = A@Wrel ; r = A@Wroot + b =======
// Split-bf16, acc = AhBh + AhBl + AlBh in fp32 (mma.sync m16n8k16).
// Block tile: 64 rows x 128 out-cols. 256 threads = 8 warps (2m x 4n).
// SPLITA: A already split to bf16 (g_hh/g_hl) -> pure coalesced copy.
template <int KD, bool SPLITA>
__global__ __launch_bounds__(256) void k_hgemm(const float* __restrict__ A,
                                               const uint32_t* __restrict__ Ahh,
                                               const uint32_t* __restrict__ All,
                                               const uint16_t* __restrict__ Bh,
                                               const uint16_t* __restrict__ Bl,
                                               const float* __restrict__ bias) {
    extern __shared__ char smem[];
    constexpr int SA = KD + 8;                       // padded row stride (bf16 elems)
    constexpr int ABYTES = 64 * SA * 2;
    constexpr int BBYTES = 128 * SA * 2;
    char* a_hi = smem;
    char* a_lo = smem + ABYTES;
    char* b_hi = smem + 2 * ABYTES;
    char* b_lo = smem + 2 * ABYTES + BBYTES;
    float* bsh = (float*)(smem + 2 * ABYTES + 2 * BBYTES);

    const int t = threadIdx.x;
    const int wid = t >> 5;
    const int lane = t & 31;
    const int row0 = blockIdx.x * 64;

    if (t < 64) bsh[t] = bias[t];

    // ---- A tile ----
    if (SPLITA) {
        // rows of 64 bf16 = 8 uint4 per row per array
        constexpr int RG = 64 * (KD / 8);
        for (int g = t; g < RG; g += 256) {
            int row = g / (KD / 8);
            int k8 = (g % (KD / 8)) * 8;
            uint4 vh = make_uint4(0, 0, 0, 0), vl = make_uint4(0, 0, 0, 0);
            if (row0 + row < N_NODES) {
                size_t gi = (size_t)(row0 + row) * (KD / 8) + (g % (KD / 8));
                vh = ((const uint4*)Ahh)[gi];
                vl = ((const uint4*)All)[gi];
            }
            uint32_t off = (uint32_t)(row * SA + k8) * 2;
            *(uint4*)(a_hi + off) = vh;
            *(uint4*)(a_lo + off) = vl;
        }
    } else {
        constexpr int G = 64 * KD / 4;
        for (int g = t; g < G; g += 256) {
            int row = g / (KD / 4);
            int k4 = (g % (KD / 4)) * 4;
            float4 v = make_float4(0.f, 0.f, 0.f, 0.f);
            if (row0 + row < N_NODES)
                v = *(const float4*)(A + (size_t)(row0 + row) * KD + k4);
            uint32_t l01, l23;
            uint32_t h01 = pack_hi(v.x, v.y, l01);
            uint32_t h23 = pack_hi(v.z, v.w, l23);
            uint32_t off = (uint32_t)(row * SA + k4) * 2;
            *(uint2*)(a_hi + off) = make_uint2(h01, h23);
            *(uint2*)(a_lo + off) = make_uint2(l01, l23);
        }
    }
    // ---- B tile: pure coalesced copy of pre-split weights ----
    {
        constexpr int G = 128 * KD / 8;   // uint4 groups
        const uint4* sh = (const uint4*)Bh;
        const uint4* sl = (const uint4*)Bl;
        for (int g = t; g < G; g += 256) {
            int n = g / (KD / 8);
            int k8 = (g % (KD / 8)) * 8;
            uint32_t off = (uint32_t)(n * SA + k8) * 2;
            *(uint4*)(b_hi + off) = sh[g];
            *(uint4*)(b_lo + off) = sl[g];
        }
    }
    __syncthreads();

    // warp tile: rows m_base..m_base+31, cols n_base..n_base+31
    const int m_base = (wid & 1) * 32;
    const int n_base = (wid >> 1) * 32;

    float c[8][4];
#pragma unroll
    for (int f = 0; f < 8; f++)
#pragma unroll
        for (int i = 0; i < 4; i++) c[f][i] = 0.f;

    const uint32_t sa_hi = smem_u32(a_hi), sa_lo = smem_u32(a_lo);
    const uint32_t sb_hi = smem_u32(b_hi), sb_lo = smem_u32(b_lo);

    const int a_row = (lane & 15);
    const int a_kof = (lane >> 4) * 8;
    const int b_row = ((lane >> 4) & 1) * 8 + (lane & 7);
    const int b_kof = ((lane >> 3) & 1) * 8;

#pragma unroll
    for (int ks = 0; ks < KD; ks += 16) {
        uint32_t ah[2][4], al[2][4];
#pragma unroll
        for (int mi = 0; mi < 2; mi++) {
            uint32_t off = (uint32_t)((m_base + mi * 16 + a_row) * SA + ks + a_kof) * 2;
            ldmx4(ah[mi][0], ah[mi][1], ah[mi][2], ah[mi][3], sa_hi + off);
            ldmx4(al[mi][0], al[mi][1], al[mi][2], al[mi][3], sa_lo + off);
        }
        uint32_t bh[4][2], bl[4][2];
#pragma unroll
        for (int nj = 0; nj < 2; nj++) {
            uint32_t off = (uint32_t)((n_base + nj * 16 + b_row) * SA + ks + b_kof) * 2;
            uint32_t r0, r1, r2, r3;
            ldmx4(r0, r1, r2, r3, sb_hi + off);
            bh[nj * 2][0] = r0; bh[nj * 2][1] = r1;
            bh[nj * 2 + 1][0] = r2; bh[nj * 2 + 1][1] = r3;
            ldmx4(r0, r1, r2, r3, sb_lo + off);
            bl[nj * 2][0] = r0; bl[nj * 2][1] = r1;
            bl[nj * 2 + 1][0] = r2; bl[nj * 2 + 1][1] = r3;
        }
#pragma unroll
        for (int mi = 0; mi < 2; mi++)
#pragma unroll
            for (int ni = 0; ni < 4; ni++) {
                float* cf = c[mi * 4 + ni];
                mma16816(cf, ah[mi], bh[ni][0], bh[ni][1]);
                mma16816(cf, ah[mi], bl[ni][0], bl[ni][1]);
                mma16816(cf, al[mi], bh[ni][0], bh[ni][1]);
            }
    }

    // ---- epilogue ----
    const int er = lane >> 2;
    const int ec = (lane & 3) * 2;
#pragma unroll
    for (int mi = 0; mi < 2; mi++) {
#pragma unroll
        for (int half = 0; half < 2; half++) {
            int m = m_base + mi * 16 + half * 8 + er;
            int node = row0 + m;
            if (node >= N_NODES) continue;
#pragma unroll
            for (int ni = 0; ni < 4; ni++) {
                int j = n_base + ni * 8 + ec;
                float v0 = c[mi * 4 + ni][half * 2 + 0];
                float v1 = c[mi * 4 + ni][half * 2 + 1];
                if (j < 64) {
                    *(float2*)(g_y + (size_t)node * 64 + j) = make_float2(v0, v1);
                } else {
                    *(float2*)(g_r + (size_t)node * 64 + (j - 64)) =
                        make_float2(v0 + bsh[j - 64], v1 + bsh[j - 63]);
                }
            }
        }
    }
}

// ---------------- aggregation: h = relu(sum_{s->i} y[s] + r[i]) -------------
// Also emits split-bf16 h for the next layer's GEMM.
__global__ void k_agg() {
    int w = (blockIdx.x * blockDim.x + threadIdx.x) >> 5;
    int lane = threadIdx.x & 31;
    if (w >= N_NODES) return;
    int beg = g_rowptr[w];
    int end = g_rowptr[w + 1];
    const float2* y2 = (const float2*)g_y;
    float2 a0 = make_float2(0.f, 0.f), a1 = make_float2(0.f, 0.f);
    int e = beg;
    for (; e + 1 < end; e += 2) {
        int s0 = __ldg(&g_col[e]);
        int s1 = __ldg(&g_col[e + 1]);
        float2 v0 = __ldg(&y2[(size_t)s0 * 32 + lane]);
        float2 v1 = __ldg(&y2[(size_t)s1 * 32 + lane]);
        a0.x += v0.x; a0.y += v0.y;
        a1.x += v1.x; a1.y += v1.y;
    }
    if (e < end) {
        int s = __ldg(&g_col[e]);
        float2 v = __ldg(&y2[(size_t)s * 32 + lane]);
        a0.x += v.x; a0.y += v.y;
    }
    float2 rv = ((const float2*)g_r)[(size_t)w * 32 + lane];
    float2 o;
    o.x = fmaxf(a0.x + a1.x + rv.x, 0.f);
    o.y = fmaxf(a0.y + a1.y + rv.y, 0.f);
    size_t gi = (size_t)w * 32 + lane;
    ((float2*)g_h)[gi] = o;
    // split-bf16 for next layer
    uint32_t lo;
    uint32_t hi = pack_hi(o.x, o.y, lo);
    g_hh[gi] = hi;
    g_hl[gi] = lo;
}

// ---------------- pooling ---------------------------------------------------
__global__ void k_zero_pool() {
    int i = blockIdx.x * blockDim.x + threadIdx.x;
    if (i < N_GRAPHS * HID) g_pool[i] = 0.f;
    if (i < N_GRAPHS) g_cnt[i] = 0.f;
}
__global__ void k_pool(const int* __restrict__ batch) {
    int chunk = (blockIdx.x * blockDim.x + threadIdx.x) >> 5;
    int lane = threadIdx.x & 31;
    int n0 = chunk * 32;
    if (n0 >= N_NODES) return;
    int n1 = min(n0 + 32, N_NODES);
    int f = g_flags[1];
    const float2* h2 = (const float2*)g_h;
    float2 acc = make_float2(0.f, 0.f);
    int cnt = 0;
    int cur = f ? batch[2 * n0] : batch[n0];
    for (int n = n0; n < n1; n++) {
        int g = f ? batch[2 * n] : batch[n];
        if (g != cur) {
            atomicAdd(&g_pool[cur * 64 + 2 * lane], acc.x);
            atomicAdd(&g_pool[cur * 64 + 2 * lane + 1], acc.y);
            if (lane == 0) atomicAdd(&g_cnt[cur], (float)cnt);
            acc = make_float2(0.f, 0.f); cnt = 0; cur = g;
        }
        float2 v = h2[(size_t)n * 32 + lane];
        acc.x += v.x; acc.y += v.y; cnt++;
    }
    atomicAdd(&g_pool[cur * 64 + 2 * lane], acc.x);
    atomicAdd(&g_pool[cur * 64 + 2 * lane + 1], acc.y);
    if (lane == 0) atomicAdd(&g_cnt[cur], (float)cnt);
}

// ---------------- head ------------------------------------------------------
__global__ void k_head(const float* __restrict__ w1, const float* __restrict__ b1,
                       const float* __restrict__ w2, const float* __restrict__ b2,
                       float* __restrict__ out) {
    __shared__ float s_w1[64 * 64], s_b1[64], s_w2[128], s_b2[2];
    int t = threadIdx.x;
    for (int i = t; i < 64 * 64; i += 64) s_w1[i] = w1[i];
    s_b1[t] = b1[t];
    for (int i = t; i < 128; i += 64) s_w2[i] = w2[i];
    if (t < 2) s_b2[t] = b2[t];
    __syncthreads();

    float cnt = fmaxf(g_cnt[t], 1.f);
    float m[64];
#pragma unroll
    for (int c = 0; c < 64; c++) m[c] = g_pool[t * 64 + c] / cnt;

    float o0 = s_b2[0], o1 = s_b2[1];
    for (int j = 0; j < 64; j++) {
        float z = s_b1[j];
#pragma unroll 8
        for (int k = 0; k < 64; k++) z += m[k] * s_w1[k * 64 + j];
        z = fmaxf(z, 0.f);
        o0 += z * s_w2[j * 2];
        o1 += z * s_w2[j * 2 + 1];
    }
    out[t * 2 + 0] = o0;
    out[t * 2 + 1] = o1;
}

// ---------------- launch ----------------------------------------------------
extern "C" void kernel_launch(void* const* d_in, const int* in_sizes, int n_in,
                              void* d_out, int out_size) {
    const float* x       = (const float*)d_in[0];
    const int*   edge    = (const int*)d_in[1];
    const int*   batch   = (const int*)d_in[2];
    const float* w_rel0  = (const float*)d_in[3];
    const float* b_rel0  = (const float*)d_in[4];
    const float* w_root0 = (const float*)d_in[5];
    const float* w_rel1  = (const float*)d_in[6];
    const float* b_rel1  = (const float*)d_in[7];
    const float* w_root1 = (const float*)d_in[8];
    const float* w_rel2  = (const float*)d_in[9];
    const float* b_rel2  = (const float*)d_in[10];
    const float* w_root2 = (const float*)d_in[11];
    const float* head_w1 = (const float*)d_in[12];
    const float* head_b1 = (const float*)d_in[13];
    const float* head_w2 = (const float*)d_in[14];
    const float* head_b2 = (const float*)d_in[15];
    float* out = (float*)d_out;

    const int E = in_sizes[1] / 2;

    const int smem128 = 2 * (64 * (128 + 8) * 2) + 2 * (128 * (128 + 8) * 2) + 256;
    const int smem64  = 2 * (64 * (64 + 8) * 2) + 2 * (128 * (64 + 8) * 2) + 256;
    cudaFuncSetAttribute((const void*)k_hgemm<128, false>,
                         cudaFuncAttributeMaxDynamicSharedMemorySize, smem128);
    cudaFuncSetAttribute((const void*)k_hgemm<64, true>,
                         cudaFuncAttributeMaxDynamicSharedMemorySize, smem64);

    void *p_h, *p_hh, *p_hl, *p_bh0, *p_bl0, *p_bh1, *p_bl1, *p_bh2, *p_bl2;
    cudaGetSymbolAddress(&p_h, g_h);
    cudaGetSymbolAddress(&p_hh, g_hh);
    cudaGetSymbolAddress(&p_hl, g_hl);
    cudaGetSymbolAddress(&p_bh0, g_bh0);
    cudaGetSymbolAddress(&p_bl0, g_bl0);
    cudaGetSymbolAddress(&p_bh1, g_bh1);
    cudaGetSymbolAddress(&p_bl1, g_bl1);
    cudaGetSymbolAddress(&p_bh2, g_bh2);
    cudaGetSymbolAddress(&p_bl2, g_bl2);

    const int gblk = (N_NODES + 63) / 64;   // 1563
    const int ablk = (N_NODES + 7) / 8;

    // one-time weight splits (tiny)
    k_bsplit<<<(128 * 128 + 255) / 256, 256>>>(w_rel0, w_root0, (uint16_t*)p_bh0, (uint16_t*)p_bl0, 128);
    k_bsplit<<<(128 * 64 + 255) / 256, 256>>>(w_rel1, w_root1, (uint16_t*)p_bh1, (uint16_t*)p_bl1, 64);
    k_bsplit<<<(128 * 64 + 255) / 256, 256>>>(w_rel2, w_root2, (uint16_t*)p_bh2, (uint16_t*)p_bl2, 64);

    // layer-0 GEMM (independent of CSR build)
    k_hgemm<128, false><<<gblk, 256, smem128>>>(x, nullptr, nullptr,
                                                (const uint16_t*)p_bh0, (const uint16_t*)p_bl0, b_rel0);

    // CSR build
    k_detect<<<2, 256>>>(edge, batch);
    k_zero_deg<<<(N_NODES + 255) / 256, 256>>>();
    k_hist<<<1024, 256>>>(edge, E);
    k_scan1<<<NSCAN_BLK, 1024>>>();
    k_scan2<<<1, 128>>>(NSCAN_BLK, E);
    k_scan3<<<NSCAN_BLK, 1024>>>();
    k_cursor<<<(N_NODES + 1023) / 1024, 1024>>>();
    k_scatter<<<1024, 256>>>(edge, E);

    // layer 0 aggregate, then layers 1 & 2
    k_agg<<<ablk, 256>>>();
    k_hgemm<64, true><<<gblk, 256, smem64>>>((const float*)p_h, (const uint32_t*)p_hh, (const uint32_t*)p_hl,
                                             (const uint16_t*)p_bh1, (const uint16_t*)p_bl1, b_rel1);
    k_agg<<<ablk, 256>>>();
    k_hgemm<64, true><<<gblk, 256, smem64>>>((const float*)p_h, (const uint32_t*)p_hh, (const uint32_t*)p_hl,
                                             (const uint16_t*)p_bh2, (const uint16_t*)p_bl2, b_rel2);
    k_agg<<<ablk, 256>>>();

    // pooling + head
    k_zero_pool<<<(N_GRAPHS * HID + 255) / 256, 256>>>();
    k_pool<<<(N_NODES / 32 * 32 + 255) / 256, 256>>>(batch);
    k_head<<<1, 64>>>(head_w1, head_b1, head_w2, head_b2, out);
}

// round 9
// speedup vs baseline: 1.5304x; 1.0905x over previous
#include <cuda_runtime.h>
#include <cuda_bf16.h>
#include <cstdint>

#define N_NODES 100000
#define N_GRAPHS 64
#define HID 64
#define MAX_E 1600000
#define NSCAN_BLK 98   // ceil(100000/1024)

// ---------------- scratch (static device globals; no runtime alloc) --------
__device__ int   g_deg[N_NODES];
__device__ int   g_rowptr[N_NODES + 1];
__device__ int   g_tmp[N_NODES];
__device__ int   g_col[MAX_E];
__device__ float g_y[N_NODES * HID];
__device__ float g_r[N_NODES * HID];
__device__ float g_h[N_NODES * HID];
__device__ uint32_t g_hh[N_NODES * HID / 2];   // h split-bf16 hi (bf16x2 packed)
__device__ uint32_t g_hl[N_NODES * HID / 2];   // h split-bf16 lo
__device__ uint16_t g_bh0[128 * 128], g_bl0[128 * 128];
__device__ uint16_t g_bh1[128 * 64],  g_bl1[128 * 64];
__device__ uint16_t g_bh2[128 * 64],  g_bl2[128 * 64];
__device__ int   g_bsum[256];
__device__ int   g_boff[256];
__device__ float g_pool[N_GRAPHS * HID];
__device__ float g_cnt[N_GRAPHS];
__device__ int   g_flags[2];

// ---------------- init: dtype detect + zero deg/pool (merged) ---------------
__global__ void k_init(const int* __restrict__ edge, const int* __restrict__ batch) {
    int i = blockIdx.x * blockDim.x + threadIdx.x;
    if (i < N_NODES) g_deg[i] = 0;
    if (i < N_GRAPHS * HID) g_pool[i] = 0.f;
    if (i < N_GRAPHS) g_cnt[i] = 0.f;
    if (blockIdx.x < 2) {
        __shared__ int s_nz;
        int t = threadIdx.x;
        if (t == 0) s_nz = 0;
        __syncthreads();
        int v;
        if (blockIdx.x == 0) v = edge[2 * t + 1];
        else                 v = batch[2 * (30000 + t * 64) + 1];
        if (v != 0) atomicOr(&s_nz, 1);
        __syncthreads();
        if (t == 0) g_flags[blockIdx.x] = (s_nz == 0) ? 1 : 0;
    }
}

// ---------------- CSR build -------------------------------------------------
__global__ void k_hist(const int* __restrict__ edge, int E) {
    int f = g_flags[0];
    int stride = gridDim.x * blockDim.x;
    for (int e = blockIdx.x * blockDim.x + threadIdx.x; e < E; e += stride) {
        int d = f ? edge[2 * (E + e)] : edge[E + e];
        atomicAdd(&g_deg[d], 1);
    }
}
__global__ void k_scan1() {
    __shared__ int sm[1024];
    int i = blockIdx.x * 1024 + threadIdx.x;
    int v = (i < N_NODES) ? g_deg[i] : 0;
    sm[threadIdx.x] = v;
    __syncthreads();
    for (int off = 1; off < 1024; off <<= 1) {
        int u = (threadIdx.x >= off) ? sm[threadIdx.x - off] : 0;
        __syncthreads();
        sm[threadIdx.x] += u;
        __syncthreads();
    }
    if (i < N_NODES) g_tmp[i] = sm[threadIdx.x];
    if (threadIdx.x == 1023) g_bsum[blockIdx.x] = sm[1023];
}
__global__ void k_scan2(int nb, int E) {
    __shared__ int sm[128];
    int t = threadIdx.x;
    int v = (t < nb) ? g_bsum[t] : 0;
    sm[t] = v;
    __syncthreads();
    for (int off = 1; off < 128; off <<= 1) {
        int u = (t >= off) ? sm[t - off] : 0;
        __syncthreads();
        sm[t] += u;
        __syncthreads();
    }
    if (t < nb) g_boff[t] = sm[t] - v;
    if (t == 0) { g_rowptr[0] = 0; g_rowptr[N_NODES] = E; }
}
// scan3 + cursor merged: rowptr[i+1] = incl[i]+boff; tmp[i] = rowptr[i] (exclusive)
__global__ void k_scan3() {
    int i = blockIdx.x * 1024 + threadIdx.x;
    if (i < N_NODES) {
        int incl = g_tmp[i] + g_boff[blockIdx.x];
        g_rowptr[i + 1] = incl;
        g_tmp[i] = incl - g_deg[i];
    }
}
__global__ void k_scatter(const int* __restrict__ edge, int E) {
    int f = g_flags[0];
    int stride = gridDim.x * blockDim.x;
    for (int e = blockIdx.x * blockDim.x + threadIdx.x; e < E; e += stride) {
        int s = f ? edge[2 * e] : edge[e];
        int d = f ? edge[2 * (E + e)] : edge[E + e];
        int pos = atomicAdd(&g_tmp[d], 1);
        g_col[pos] = s;
    }
}

// ================= HMMA helpers (plain sm_80+ PTX) =========================
__device__ __forceinline__ uint32_t smem_u32(const void* p) {
    uint32_t a;
    asm("{ .reg .u64 t; cvta.to.shared.u64 t, %1; cvt.u32.u64 %0, t; }" : "=r"(a) : "l"(p));
    return a;
}
__device__ __forceinline__ void ldmx4(uint32_t& r0, uint32_t& r1, uint32_t& r2, uint32_t& r3,
                                      uint32_t addr) {
    asm volatile("ldmatrix.sync.aligned.m8n8.x4.shared.b16 {%0,%1,%2,%3}, [%4];"
                 : "=r"(r0), "=r"(r1), "=r"(r2), "=r"(r3) : "r"(addr));
}
__device__ __forceinline__ void mma16816(float* c, const uint32_t* a, uint32_t b0, uint32_t b1) {
    asm volatile("mma.sync.aligned.m16n8k16.row.col.f32.bf16.bf16.f32 "
                 "{%0,%1,%2,%3}, {%4,%5,%6,%7}, {%8,%9}, {%0,%1,%2,%3};"
                 : "+f"(c[0]), "+f"(c[1]), "+f"(c[2]), "+f"(c[3])
                 : "r"(a[0]), "r"(a[1]), "r"(a[2]), "r"(a[3]), "r"(b0), "r"(b1));
}
__device__ __forceinline__ uint32_t pack_hi(float x, float y, uint32_t& lo) {
    __nv_bfloat16 hx = __float2bfloat16(x);
    __nv_bfloat16 hy = __float2bfloat16(y);
    __nv_bfloat16 lx = __float2bfloat16(x - __bfloat162float(hx));
    __nv_bfloat16 ly = __float2bfloat16(y - __bfloat162float(hy));
    __nv_bfloat162 l2 = make_bfloat162(lx, ly);
    __nv_bfloat162 h2 = make_bfloat162(hx, hy);
    lo = *(uint32_t*)&l2;
    return *(uint32_t*)&h2;
}

// ---------------- one-time weight split: W -> Bh/Bl [128][KD] bf16 ----------
__global__ void k_bsplit(const float* __restrict__ Wrel, const float* __restrict__ Wroot,
                         uint16_t* __restrict__ bh, uint16_t* __restrict__ bl, int KD) {
    int idx = blockIdx.x * blockDim.x + threadIdx.x;   // idx = k*128 + n (coalesced read)
    if (idx >= 128 * KD) return;
    int k = idx >> 7, n = idx & 127;
    float v = (n < 64) ? Wrel[k * 64 + n] : Wroot[k * 64 + (n - 64)];
    __nv_bfloat16 h = __float2bfloat16(v);
    __nv_bfloat16 l = __float2bfloat16(v - __bfloat162float(h));
    bh[n * KD + k] = *(uint16_t*)&h;
    bl[n * KD + k] = *(uint16_t*)&l;
}

// =============== tensor-core fused GEMM: y = A@Wrel ; r = A@Wroot + b =======
// Split-bf16, acc = AhBh + AhBl + AlBh in fp32 (mma.sync m16n8k16).
// Block tile: 64 rows x 128 out-cols. 256 threads = 8 warps (2m x 4n).
// K processed in CHUNKS passes of 64 over a 64-wide smem stage -> ~55KB smem
// -> 4 blocks/SM for all layers (incl. KD=128 layer 0).
// SPLITA: A already split to bf16 (g_hh/g_hl) -> pure coalesced copy (CHUNKS==1).
template <int CHUNKS, bool SPLITA>
__global__ __launch_bounds__(256) void k_hgemm(const float* __restrict__ A,
                                               const uint32_t* __restrict__ Ahh,
                                               const uint32_t* __restrict__ All,
                                               const uint16_t* __restrict__ Bh,
                                               const uint16_t* __restrict__ Bl,
                                               const float* __restrict__ bias) {
    extern __shared__ char smem[];
    constexpr int KD = CHUNKS * 64;                  // logical K
    constexpr int SA = 64 + 8;                       // padded stage row stride (bf16)
    constexpr int ABYTES = 64 * SA * 2;
    constexpr int BBYTES = 128 * SA * 2;
    char* a_hi = smem;
    char* a_lo = smem + ABYTES;
    char* b_hi = smem + 2 * ABYTES;
    char* b_lo = smem + 2 * ABYTES + BBYTES;
    float* bsh = (float*)(smem + 2 * ABYTES + 2 * BBYTES);

    const int t = threadIdx.x;
    const int wid = t >> 5;
    const int lane = t & 31;
    const int row0 = blockIdx.x * 64;

    if (t < 64) bsh[t] = bias[t];

    const int m_base = (wid & 1) * 32;
    const int n_base = (wid >> 1) * 32;

    float c[8][4];
#pragma unroll
    for (int f = 0; f < 8; f++)
#pragma unroll
        for (int i = 0; i < 4; i++) c[f][i] = 0.f;

    const uint32_t sa_hi = smem_u32(a_hi), sa_lo = smem_u32(a_lo);
    const uint32_t sb_hi = smem_u32(b_hi), sb_lo = smem_u32(b_lo);

    const int a_row = (lane & 15);
    const int a_kof = (lane >> 4) * 8;
    const int b_row = ((lane >> 4) & 1) * 8 + (lane & 7);
    const int b_kof = ((lane >> 3) & 1) * 8;

#pragma unroll
    for (int chunk = 0; chunk < CHUNKS; chunk++) {
        if (chunk > 0) __syncthreads();   // smem stage reuse barrier

        // ---- A stage: 64 rows x 64 k-cols ----
        if (SPLITA) {
            // 8 uint4 per row per array (64 bf16)
            for (int g = t; g < 64 * 8; g += 256) {
                int row = g >> 3;
                int j = g & 7;
                uint4 vh = make_uint4(0, 0, 0, 0), vl = make_uint4(0, 0, 0, 0);
                if (row0 + row < N_NODES) {
                    size_t gi = (size_t)(row0 + row) * 8 + j;
                    vh = ((const uint4*)Ahh)[gi];
                    vl = ((const uint4*)All)[gi];
                }
                uint32_t off = (uint32_t)(row * SA + j * 8) * 2;
                *(uint4*)(a_hi + off) = vh;
                *(uint4*)(a_lo + off) = vl;
            }
        } else {
            for (int g = t; g < 64 * 16; g += 256) {
                int row = g >> 4;
                int k4 = (g & 15) * 4;
                float4 v = make_float4(0.f, 0.f, 0.f, 0.f);
                if (row0 + row < N_NODES)
                    v = *(const float4*)(A + (size_t)(row0 + row) * KD + chunk * 64 + k4);
                uint32_t l01, l23;
                uint32_t h01 = pack_hi(v.x, v.y, l01);
                uint32_t h23 = pack_hi(v.z, v.w, l23);
                uint32_t off = (uint32_t)(row * SA + k4) * 2;
                *(uint2*)(a_hi + off) = make_uint2(h01, h23);
                *(uint2*)(a_lo + off) = make_uint2(l01, l23);
            }
        }
        // ---- B stage: 128 n-rows x 64 k-cols (coalesced copy of pre-split) --
        {
            for (int g = t; g < 128 * 8; g += 256) {
                int n = g >> 3;
                int j = g & 7;
                size_t gi = (size_t)n * (KD / 8) + chunk * 8 + j;
                uint32_t off = (uint32_t)(n * SA + j * 8) * 2;
                *(uint4*)(b_hi + off) = ((const uint4*)Bh)[gi];
                *(uint4*)(b_lo + off) = ((const uint4*)Bl)[gi];
            }
        }
        __syncthreads();

#pragma unroll
        for (int ks = 0; ks < 64; ks += 16) {
            uint32_t ah[2][4], al[2][4];
#pragma unroll
            for (int mi = 0; mi < 2; mi++) {
                uint32_t off = (uint32_t)((m_base + mi * 16 + a_row) * SA + ks + a_kof) * 2;
                ldmx4(ah[mi][0], ah[mi][1], ah[mi][2], ah[mi][3], sa_hi + off);
                ldmx4(al[mi][0], al[mi][1], al[mi][2], al[mi][3], sa_lo + off);
            }
            uint32_t bh[4][2], bl[4][2];
#pragma unroll
            for (int nj = 0; nj < 2; nj++) {
                uint32_t off = (uint32_t)((n_base + nj * 16 + b_row) * SA + ks + b_kof) * 2;
                uint32_t r0, r1, r2, r3;
                ldmx4(r0, r1, r2, r3, sb_hi + off);
                bh[nj * 2][0] = r0; bh[nj * 2][1] = r1;
                bh[nj * 2 + 1][0] = r2; bh[nj * 2 + 1][1] = r3;
                ldmx4(r0, r1, r2, r3, sb_lo + off);
                bl[nj * 2][0] = r0; bl[nj * 2][1] = r1;
                bl[nj * 2 + 1][0] = r2; bl[nj * 2 + 1][1] = r3;
            }
#pragma unroll
            for (int mi = 0; mi < 2; mi++)
#pragma unroll
                for (int ni = 0; ni < 4; ni++) {
                    float* cf = c[mi * 4 + ni];
                    mma16816(cf, ah[mi], bh[ni][0], bh[ni][1]);
                    mma16816(cf, ah[mi], bl[ni][0], bl[ni][1]);
                    mma16816(cf, al[mi], bh[ni][0], bh[ni][1]);
                }
        }
    }

    // ---- epilogue ----
    const int er = lane >> 2;
    const int ec = (lane & 3) * 2;
#pragma unroll
    for (int mi = 0; mi < 2; mi++) {
#pragma unroll
        for (int half = 0; half < 2; half++) {
            int m = m_base + mi * 16 + half * 8 + er;
            int node = row0 + m;
            if (node >= N_NODES) continue;
#pragma unroll
            for (int ni = 0; ni < 4; ni++) {
                int j = n_base + ni * 8 + ec;
                float v0 = c[mi * 4 + ni][half * 2 + 0];
                float v1 = c[mi * 4 + ni][half * 2 + 1];
                if (j < 64) {
                    *(float2*)(g_y + (size_t)node * 64 + j) = make_float2(v0, v1);
                } else {
                    *(float2*)(g_r + (size_t)node * 64 + (j - 64)) =
                        make_float2(v0 + bsh[j - 64], v1 + bsh[j - 63]);
                }
            }
        }
    }
}

// ---------------- aggregation: h = relu(sum_{s->i} y[s] + r[i]) -------------
// EMIT_SPLIT: write split-bf16 h (consumed by next layer's GEMM)
// EMIT_F32:   write fp32 h (consumed by pooling, last layer only)
template <bool EMIT_SPLIT, bool EMIT_F32>
__global__ void k_agg() {
    int w = (blockIdx.x * blockDim.x + threadIdx.x) >> 5;
    int lane = threadIdx.x & 31;
    if (w >= N_NODES) return;
    int beg = g_rowptr[w];
    int end = g_rowptr[w + 1];
    const float2* y2 = (const float2*)g_y;
    float2 a0 = make_float2(0.f, 0.f), a1 = make_float2(0.f, 0.f);
    int e = beg;
    for (; e + 1 < end; e += 2) {
        int s0 = __ldg(&g_col[e]);
        int s1 = __ldg(&g_col[e + 1]);
        float2 v0 = __ldg(&y2[(size_t)s0 * 32 + lane]);
        float2 v1 = __ldg(&y2[(size_t)s1 * 32 + lane]);
        a0.x += v0.x; a0.y += v0.y;
        a1.x += v1.x; a1.y += v1.y;
    }
    if (e < end) {
        int s = __ldg(&g_col[e]);
        float2 v = __ldg(&y2[(size_t)s * 32 + lane]);
        a0.x += v.x; a0.y += v.y;
    }
    float2 rv = ((const float2*)g_r)[(size_t)w * 32 + lane];
    float2 o;
    o.x = fmaxf(a0.x + a1.x + rv.x, 0.f);
    o.y = fmaxf(a0.y + a1.y + rv.y, 0.f);
    size_t gi = (size_t)w * 32 + lane;
    if (EMIT_F32) ((float2*)g_h)[gi] = o;
    if (EMIT_SPLIT) {
        uint32_t lo;
        uint32_t hi = pack_hi(o.x, o.y, lo);
        g_hh[gi] = hi;
        g_hl[gi] = lo;
    }
}

// ---------------- pooling ---------------------------------------------------
__global__ void k_pool(const int* __restrict__ batch) {
    int chunk = (blockIdx.x * blockDim.x + threadIdx.x) >> 5;
    int lane = threadIdx.x & 31;
    int n0 = chunk * 32;
    if (n0 >= N_NODES) return;
    int n1 = min(n0 + 32, N_NODES);
    int f = g_flags[1];
    const float2* h2 = (const float2*)g_h;
    float2 acc = make_float2(0.f, 0.f);
    int cnt = 0;
    int cur = f ? batch[2 * n0] : batch[n0];
    for (int n = n0; n < n1; n++) {
        int g = f ? batch[2 * n] : batch[n];
        if (g != cur) {
            atomicAdd(&g_pool[cur * 64 + 2 * lane], acc.x);
            atomicAdd(&g_pool[cur * 64 + 2 * lane + 1], acc.y);
            if (lane == 0) atomicAdd(&g_cnt[cur], (float)cnt);
            acc = make_float2(0.f, 0.f); cnt = 0; cur = g;
        }
        float2 v = h2[(size_t)n * 32 + lane];
        acc.x += v.x; acc.y += v.y; cnt++;
    }
    atomicAdd(&g_pool[cur * 64 + 2 * lane], acc.x);
    atomicAdd(&g_pool[cur * 64 + 2 * lane + 1], acc.y);
    if (lane == 0) atomicAdd(&g_cnt[cur], (float)cnt);
}

// ---------------- head ------------------------------------------------------
__global__ void k_head(const float* __restrict__ w1, const float* __restrict__ b1,
                       const float* __restrict__ w2, const float* __restrict__ b2,
                       float* __restrict__ out) {
    __shared__ float s_w1[64 * 64], s_b1[64], s_w2[128], s_b2[2];
    int t = threadIdx.x;
    for (int i = t; i < 64 * 64; i += 64) s_w1[i] = w1[i];
    s_b1[t] = b1[t];
    for (int i = t; i < 128; i += 64) s_w2[i] = w2[i];
    if (t < 2) s_b2[t] = b2[t];
    __syncthreads();

    float cnt = fmaxf(g_cnt[t], 1.f);
    float m[64];
#pragma unroll
    for (int c = 0; c < 64; c++) m[c] = g_pool[t * 64 + c] / cnt;

    float o0 = s_b2[0], o1 = s_b2[1];
    for (int j = 0; j < 64; j++) {
        float z = s_b1[j];
#pragma unroll 8
        for (int k = 0; k < 64; k++) z += m[k] * s_w1[k * 64 + j];
        z = fmaxf(z, 0.f);
        o0 += z * s_w2[j * 2];
        o1 += z * s_w2[j * 2 + 1];
    }
    out[t * 2 + 0] = o0;
    out[t * 2 + 1] = o1;
}

// ---------------- launch ----------------------------------------------------
extern "C" void kernel_launch(void* const* d_in, const int* in_sizes, int n_in,
                              void* d_out, int out_size) {
    const float* x       = (const float*)d_in[0];
    const int*   edge    = (const int*)d_in[1];
    const int*   batch   = (const int*)d_in[2];
    const float* w_rel0  = (const float*)d_in[3];
    const float* b_rel0  = (const float*)d_in[4];
    const float* w_root0 = (const float*)d_in[5];
    const float* w_rel1  = (const float*)d_in[6];
    const float* b_rel1  = (const float*)d_in[7];
    const float* w_root1 = (const float*)d_in[8];
    const float* w_rel2  = (const float*)d_in[9];
    const float* b_rel2  = (const float*)d_in[10];
    const float* w_root2 = (const float*)d_in[11];
    const float* head_w1 = (const float*)d_in[12];
    const float* head_b1 = (const float*)d_in[13];
    const float* head_w2 = (const float*)d_in[14];
    const float* head_b2 = (const float*)d_in[15];
    float* out = (float*)d_out;

    const int E = in_sizes[1] / 2;

    // stage smem: 2*A(64x72) + 2*B(128x72) bf16 + bias
    const int smem_stage = 2 * (64 * 72 * 2) + 2 * (128 * 72 * 2) + 256;   // 55552
    cudaFuncSetAttribute((const void*)k_hgemm<2, false>,
                         cudaFuncAttributeMaxDynamicSharedMemorySize, smem_stage);
    cudaFuncSetAttribute((const void*)k_hgemm<1, true>,
                         cudaFuncAttributeMaxDynamicSharedMemorySize, smem_stage);

    void *p_hh, *p_hl, *p_bh0, *p_bl0, *p_bh1, *p_bl1, *p_bh2, *p_bl2;
    cudaGetSymbolAddress(&p_hh, g_hh);
    cudaGetSymbolAddress(&p_hl, g_hl);
    cudaGetSymbolAddress(&p_bh0, g_bh0);
    cudaGetSymbolAddress(&p_bl0, g_bl0);
    cudaGetSymbolAddress(&p_bh1, g_bh1);
    cudaGetSymbolAddress(&p_bl1, g_bl1);
    cudaGetSymbolAddress(&p_bh2, g_bh2);
    cudaGetSymbolAddress(&p_bl2, g_bl2);

    const int gblk = (N_NODES + 63) / 64;   // 1563
    const int ablk = (N_NODES + 7) / 8;

    // one-time weight splits (tiny)
    k_bsplit<<<(128 * 128 + 255) / 256, 256>>>(w_rel0, w_root0, (uint16_t*)p_bh0, (uint16_t*)p_bl0, 128);
    k_bsplit<<<(128 * 64 + 255) / 256, 256>>>(w_rel1, w_root1, (uint16_t*)p_bh1, (uint16_t*)p_bl1, 64);
    k_bsplit<<<(128 * 64 + 255) / 256, 256>>>(w_rel2, w_root2, (uint16_t*)p_bh2, (uint16_t*)p_bl2, 64);

    // layer-0 GEMM (independent of CSR build)
    k_hgemm<2, false><<<gblk, 256, smem_stage>>>(x, nullptr, nullptr,
                                                 (const uint16_t*)p_bh0, (const uint16_t*)p_bl0, b_rel0);

    // CSR build
    k_init<<<(N_NODES + 255) / 256, 256>>>(edge, batch);
    k_hist<<<1024, 256>>>(edge, E);
    k_scan1<<<NSCAN_BLK, 1024>>>();
    k_scan2<<<1, 128>>>(NSCAN_BLK, E);
    k_scan3<<<NSCAN_BLK, 1024>>>();
    k_scatter<<<1024, 256>>>(edge, E);

    // layer 0 aggregate, then layers 1 & 2
    k_agg<true, false><<<ablk, 256>>>();
    k_hgemm<1, true><<<gblk, 256, smem_stage>>>(nullptr, (const uint32_t*)p_hh, (const uint32_t*)p_hl,
                                                (const uint16_t*)p_bh1, (const uint16_t*)p_bl1, b_rel1);
    k_agg<true, false><<<ablk, 256>>>();
    k_hgemm<1, true><<<gblk, 256, smem_stage>>>(nullptr, (const uint32_t*)p_hh, (const uint32_t*)p_hl,
                                                (const uint16_t*)p_bh2, (const uint16_t*)p_bl2, b_rel2);
    k_agg<false, true><<<ablk, 256>>>();

    // pooling + head
    k_pool<<<(N_NODES / 32 * 32 + 255) / 256, 256>>>(batch);
    k_head<<<1, 64>>>(head_w1, head_b1, head_w2, head_b2, out);
}

// round 11
// speedup vs baseline: 1.5577x; 1.0178x over previous
#include <cuda_runtime.h>
#include <cuda_bf16.h>
#include <cstdint>

#define N_NODES 100000
#define N_GRAPHS 64
#define HID 64
#define MAX_E 1600000
#define NSCAN_BLK 98   // ceil(100000/1024)

// ---------------- scratch (static device globals; no runtime alloc) --------
__device__ int   g_deg[N_NODES];
__device__ int   g_rowptr[N_NODES + 1];
__device__ int   g_tmp[N_NODES];
__device__ int   g_col[MAX_E];
__device__ float g_y[N_NODES * HID];
__device__ float g_r[N_NODES * HID];
__device__ float g_h[N_NODES * HID];
__device__ uint32_t g_hh[N_NODES * HID / 2];   // h split-bf16 hi (bf16x2 packed)
__device__ uint32_t g_hl[N_NODES * HID / 2];   // h split-bf16 lo
__device__ uint16_t g_bh0[128 * 128], g_bl0[128 * 128];
__device__ uint16_t g_bh1[128 * 64],  g_bl1[128 * 64];
__device__ uint16_t g_bh2[128 * 64],  g_bl2[128 * 64];
__device__ int   g_bsum[256];
__device__ int   g_boff[256];
__device__ float g_pool[N_GRAPHS * HID];
__device__ float g_cnt[N_GRAPHS];
__device__ int   g_flags[2];

// ---------------- init: dtype detect + zero deg/pool (merged) ---------------
__global__ void k_init(const int* __restrict__ edge, const int* __restrict__ batch) {
    int i = blockIdx.x * blockDim.x + threadIdx.x;
    if (i < N_NODES) g_deg[i] = 0;
    if (i < N_GRAPHS * HID) g_pool[i] = 0.f;
    if (i < N_GRAPHS) g_cnt[i] = 0.f;
    if (blockIdx.x < 2) {
        __shared__ int s_nz;
        int t = threadIdx.x;
        if (t == 0) s_nz = 0;
        __syncthreads();
        int v;
        if (blockIdx.x == 0) v = edge[2 * t + 1];
        else                 v = batch[2 * (30000 + t * 64) + 1];
        if (v != 0) atomicOr(&s_nz, 1);
        __syncthreads();
        if (t == 0) g_flags[blockIdx.x] = (s_nz == 0) ? 1 : 0;
    }
}

// ---------------- CSR build -------------------------------------------------
__global__ void k_hist(const int* __restrict__ edge, int E) {
    int f = g_flags[0];
    int stride = gridDim.x * blockDim.x;
    for (int e = blockIdx.x * blockDim.x + threadIdx.x; e < E; e += stride) {
        int d = f ? edge[2 * (E + e)] : edge[E + e];
        atomicAdd(&g_deg[d], 1);
    }
}
__global__ void k_scan1() {
    __shared__ int sm[1024];
    int i = blockIdx.x * 1024 + threadIdx.x;
    int v = (i < N_NODES) ? g_deg[i] : 0;
    sm[threadIdx.x] = v;
    __syncthreads();
    for (int off = 1; off < 1024; off <<= 1) {
        int u = (threadIdx.x >= off) ? sm[threadIdx.x - off] : 0;
        __syncthreads();
        sm[threadIdx.x] += u;
        __syncthreads();
    }
    if (i < N_NODES) g_tmp[i] = sm[threadIdx.x];
    if (threadIdx.x == 1023) g_bsum[blockIdx.x] = sm[1023];
}
__global__ void k_scan2(int nb, int E) {
    __shared__ int sm[128];
    int t = threadIdx.x;
    int v = (t < nb) ? g_bsum[t] : 0;
    sm[t] = v;
    __syncthreads();
    for (int off = 1; off < 128; off <<= 1) {
        int u = (t >= off) ? sm[t - off] : 0;
        __syncthreads();
        sm[t] += u;
        __syncthreads();
    }
    if (t < nb) g_boff[t] = sm[t] - v;
    if (t == 0) { g_rowptr[0] = 0; g_rowptr[N_NODES] = E; }
}
// scan3 + cursor merged: rowptr[i+1] = incl[i]+boff; tmp[i] = rowptr[i] (exclusive)
__global__ void k_scan3() {
    int i = blockIdx.x * 1024 + threadIdx.x;
    if (i < N_NODES) {
        int incl = g_tmp[i] + g_boff[blockIdx.x];
        g_rowptr[i + 1] = incl;
        g_tmp[i] = incl - g_deg[i];
    }
}
__global__ void k_scatter(const int* __restrict__ edge, int E) {
    int f = g_flags[0];
    int stride = gridDim.x * blockDim.x;
    for (int e = blockIdx.x * blockDim.x + threadIdx.x; e < E; e += stride) {
        int s = f ? edge[2 * e] : edge[e];
        int d = f ? edge[2 * (E + e)] : edge[E + e];
        int pos = atomicAdd(&g_tmp[d], 1);
        g_col[pos] = s;
    }
}

// ================= HMMA helpers (plain sm_80+ PTX) =========================
__device__ __forceinline__ uint32_t smem_u32(const void* p) {
    uint32_t a;
    asm("{ .reg .u64 t; cvta.to.shared.u64 t, %1; cvt.u32.u64 %0, t; }" : "=r"(a) : "l"(p));
    return a;
}
__device__ __forceinline__ void ldmx4(uint32_t& r0, uint32_t& r1, uint32_t& r2, uint32_t& r3,
                                      uint32_t addr) {
    asm volatile("ldmatrix.sync.aligned.m8n8.x4.shared.b16 {%0,%1,%2,%3}, [%4];"
                 : "=r"(r0), "=r"(r1), "=r"(r2), "=r"(r3) : "r"(addr));
}
__device__ __forceinline__ void mma16816(float* c, const uint32_t* a, uint32_t b0, uint32_t b1) {
    asm volatile("mma.sync.aligned.m16n8k16.row.col.f32.bf16.bf16.f32 "
                 "{%0,%1,%2,%3}, {%4,%5,%6,%7}, {%8,%9}, {%0,%1,%2,%3};"
                 : "+f"(c[0]), "+f"(c[1]), "+f"(c[2]), "+f"(c[3])
                 : "r"(a[0]), "r"(a[1]), "r"(a[2]), "r"(a[3]), "r"(b0), "r"(b1));
}
__device__ __forceinline__ uint32_t pack_hi(float x, float y, uint32_t& lo) {
    __nv_bfloat16 hx = __float2bfloat16(x);
    __nv_bfloat16 hy = __float2bfloat16(y);
    __nv_bfloat16 lx = __float2bfloat16(x - __bfloat162float(hx));
    __nv_bfloat16 ly = __float2bfloat16(y - __bfloat162float(hy));
    __nv_bfloat162 l2 = make_bfloat162(lx, ly);
    __nv_bfloat162 h2 = make_bfloat162(hx, hy);
    lo = *(uint32_t*)&l2;
    return *(uint32_t*)&h2;
}

// ---------------- one-time weight splits (all 3 layers in one launch) -------
// segment 0: layer0 (KD=128) 16384 elems; segments 1,2: layers 1,2 (KD=64) 8192 each
__global__ void k_bsplit_all(const float* __restrict__ Wrel0, const float* __restrict__ Wroot0,
                             const float* __restrict__ Wrel1, const float* __restrict__ Wroot1,
                             const float* __restrict__ Wrel2, const float* __restrict__ Wroot2,
                             uint16_t* __restrict__ bh0, uint16_t* __restrict__ bl0,
                             uint16_t* __restrict__ bh1, uint16_t* __restrict__ bl1,
                             uint16_t* __restrict__ bh2, uint16_t* __restrict__ bl2) {
    int idx = blockIdx.x * blockDim.x + threadIdx.x;
    const float* Wrel; const float* Wroot; uint16_t* bh; uint16_t* bl; int KD;
    if (idx < 128 * 128) {
        Wrel = Wrel0; Wroot = Wroot0; bh = bh0; bl = bl0; KD = 128;
    } else if (idx < 128 * 128 + 128 * 64) {
        idx -= 128 * 128;
        Wrel = Wrel1; Wroot = Wroot1; bh = bh1; bl = bl1; KD = 64;
    } else if (idx < 128 * 128 + 2 * 128 * 64) {
        idx -= 128 * 128 + 128 * 64;
        Wrel = Wrel2; Wroot = Wroot2; bh = bh2; bl = bl2; KD = 64;
    } else return;
    int k = idx >> 7, n = idx & 127;
    float v = (n < 64) ? Wrel[k * 64 + n] : Wroot[k * 64 + (n - 64)];
    __nv_bfloat16 h = __float2bfloat16(v);
    __nv_bfloat16 l = __float2bfloat16(v - __bfloat162float(h));
    bh[n * KD + k] = *(uint16_t*)&h;
    bl[n * KD + k] = *(uint16_t*)&l;
}

// =============== tensor-core fused GEMM: y = A@Wrel ; r = A@Wroot + b =======
// Split-bf16, acc = AhBh + AhBl + AlBh in fp32 (mma.sync m16n8k16).
// Block tile: 64 rows x 128 out-cols. 256 threads = 8 warps (2m x 4n).
// K processed in CHUNKS passes of 64 over a 64-wide smem stage -> ~55KB smem
// -> 4 blocks/SM. SPLITA: A already split to bf16 -> pure coalesced copy.
template <int CHUNKS, bool SPLITA>
__global__ __launch_bounds__(256) void k_hgemm(const float* __restrict__ A,
                                               const uint32_t* __restrict__ Ahh,
                                               const uint32_t* __restrict__ All,
                                               const uint16_t* __restrict__ Bh,
                                               const uint16_t* __restrict__ Bl,
                                               const float* __restrict__ bias) {
    extern __shared__ char smem[];
    constexpr int KD = CHUNKS * 64;                  // logical K
    constexpr int SA = 64 + 8;                       // padded stage row stride (bf16)
    constexpr int ABYTES = 64 * SA * 2;
    constexpr int BBYTES = 128 * SA * 2;
    char* a_hi = smem;
    char* a_lo = smem + ABYTES;
    char* b_hi = smem + 2 * ABYTES;
    char* b_lo = smem + 2 * ABYTES + BBYTES;
    float* bsh = (float*)(smem + 2 * ABYTES + 2 * BBYTES);

    const int t = threadIdx.x;
    const int wid = t >> 5;
    const int lane = t & 31;
    const int row0 = blockIdx.x * 64;

    if (t < 64) bsh[t] = bias[t];

    const int m_base = (wid & 1) * 32;
    const int n_base = (wid >> 1) * 32;

    float c[8][4];
#pragma unroll
    for (int f = 0; f < 8; f++)
#pragma unroll
        for (int i = 0; i < 4; i++) c[f][i] = 0.f;

    const uint32_t sa_hi = smem_u32(a_hi), sa_lo = smem_u32(a_lo);
    const uint32_t sb_hi = smem_u32(b_hi), sb_lo = smem_u32(b_lo);

    const int a_row = (lane & 15);
    const int a_kof = (lane >> 4) * 8;
    const int b_row = ((lane >> 4) & 1) * 8 + (lane & 7);
    const int b_kof = ((lane >> 3) & 1) * 8;

#pragma unroll
    for (int chunk = 0; chunk < CHUNKS; chunk++) {
        if (chunk > 0) __syncthreads();   // smem stage reuse barrier

        // ---- A stage: 64 rows x 64 k-cols ----
        if (SPLITA) {
            for (int g = t; g < 64 * 8; g += 256) {
                int row = g >> 3;
                int j = g & 7;
                uint4 vh = make_uint4(0, 0, 0, 0), vl = make_uint4(0, 0, 0, 0);
                if (row0 + row < N_NODES) {
                    size_t gi = (size_t)(row0 + row) * 8 + j;
                    vh = ((const uint4*)Ahh)[gi];
                    vl = ((const uint4*)All)[gi];
                }
                uint32_t off = (uint32_t)(row * SA + j * 8) * 2;
                *(uint4*)(a_hi + off) = vh;
                *(uint4*)(a_lo + off) = vl;
            }
        } else {
            for (int g = t; g < 64 * 16; g += 256) {
                int row = g >> 4;
                int k4 = (g & 15) * 4;
                float4 v = make_float4(0.f, 0.f, 0.f, 0.f);
                if (row0 + row < N_NODES)
                    v = *(const float4*)(A + (size_t)(row0 + row) * KD + chunk * 64 + k4);
                uint32_t l01, l23;
                uint32_t h01 = pack_hi(v.x, v.y, l01);
                uint32_t h23 = pack_hi(v.z, v.w, l23);
                uint32_t off = (uint32_t)(row * SA + k4) * 2;
                *(uint2*)(a_hi + off) = make_uint2(h01, h23);
                *(uint2*)(a_lo + off) = make_uint2(l01, l23);
            }
        }
        // ---- B stage: 128 n-rows x 64 k-cols (coalesced copy of pre-split) --
        {
            for (int g = t; g < 128 * 8; g += 256) {
                int n = g >> 3;
                int j = g & 7;
                size_t gi = (size_t)n * (KD / 8) + chunk * 8 + j;
                uint32_t off = (uint32_t)(n * SA + j * 8) * 2;
                *(uint4*)(b_hi + off) = ((const uint4*)Bh)[gi];
                *(uint4*)(b_lo + off) = ((const uint4*)Bl)[gi];
            }
        }
        __syncthreads();

#pragma unroll
        for (int ks = 0; ks < 64; ks += 16) {
            uint32_t ah[2][4], al[2][4];
#pragma unroll
            for (int mi = 0; mi < 2; mi++) {
                uint32_t off = (uint32_t)((m_base + mi * 16 + a_row) * SA + ks + a_kof) * 2;
                ldmx4(ah[mi][0], ah[mi][1], ah[mi][2], ah[mi][3], sa_hi + off);
                ldmx4(al[mi][0], al[mi][1], al[mi][2], al[mi][3], sa_lo + off);
            }
            uint32_t bh[4][2], bl[4][2];
#pragma unroll
            for (int nj = 0; nj < 2; nj++) {
                uint32_t off = (uint32_t)((n_base + nj * 16 + b_row) * SA + ks + b_kof) * 2;
                uint32_t r0, r1, r2, r3;
                ldmx4(r0, r1, r2, r3, sb_hi + off);
                bh[nj * 2][0] = r0; bh[nj * 2][1] = r1;
                bh[nj * 2 + 1][0] = r2; bh[nj * 2 + 1][1] = r3;
                ldmx4(r0, r1, r2, r3, sb_lo + off);
                bl[nj * 2][0] = r0; bl[nj * 2][1] = r1;
                bl[nj * 2 + 1][0] = r2; bl[nj * 2 + 1][1] = r3;
            }
#pragma unroll
            for (int mi = 0; mi < 2; mi++)
#pragma unroll
                for (int ni = 0; ni < 4; ni++) {
                    float* cf = c[mi * 4 + ni];
                    mma16816(cf, ah[mi], bh[ni][0], bh[ni][1]);
                    mma16816(cf, ah[mi], bl[ni][0], bl[ni][1]);
                    mma16816(cf, al[mi], bh[ni][0], bh[ni][1]);
                }
        }
    }

    // ---- epilogue ----
    const int er = lane >> 2;
    const int ec = (lane & 3) * 2;
#pragma unroll
    for (int mi = 0; mi < 2; mi++) {
#pragma unroll
        for (int half = 0; half < 2; half++) {
            int m = m_base + mi * 16 + half * 8 + er;
            int node = row0 + m;
            if (node >= N_NODES) continue;
#pragma unroll
            for (int ni = 0; ni < 4; ni++) {
                int j = n_base + ni * 8 + ec;
                float v0 = c[mi * 4 + ni][half * 2 + 0];
                float v1 = c[mi * 4 + ni][half * 2 + 1];
                if (j < 64) {
                    *(float2*)(g_y + (size_t)node * 64 + j) = make_float2(v0, v1);
                } else {
                    *(float2*)(g_r + (size_t)node * 64 + (j - 64)) =
                        make_float2(v0 + bsh[j - 64], v1 + bsh[j - 63]);
                }
            }
        }
    }
}

// ---------------- aggregation: h = relu(sum_{s->i} y[s] + r[i]) -------------
// Half-warp per edge: lanes 0-15 -> edge e, lanes 16-31 -> edge e+1, each lane
// loads a float4 (channels 4*kk..4*kk+3). Two accumulator sets process 4 edges
// per iteration (MLP=4, half the LDG instructions of the float2 version).
// EMIT_SPLIT: write split-bf16 h (next layer's GEMM); EMIT_F32: write fp32 h.
template <bool EMIT_SPLIT, bool EMIT_F32>
__global__ void k_agg() {
    int w = (blockIdx.x * blockDim.x + threadIdx.x) >> 5;
    if (w >= N_NODES) return;                 // uniform per warp
    const int lane = threadIdx.x & 31;
    const int half = lane >> 4;               // which edge of the pair
    const int kk = lane & 15;                 // float4 channel group
    const int beg = g_rowptr[w];
    const int end = g_rowptr[w + 1];
    const float4* y4 = (const float4*)g_y;

    float4 a0 = make_float4(0.f, 0.f, 0.f, 0.f);
    float4 a1 = make_float4(0.f, 0.f, 0.f, 0.f);
    int e = beg;
    for (; e + 3 < end; e += 4) {
        int s0 = __ldg(&g_col[e + half]);
        int s1 = __ldg(&g_col[e + 2 + half]);
        float4 v0 = __ldg(&y4[(size_t)s0 * 16 + kk]);
        float4 v1 = __ldg(&y4[(size_t)s1 * 16 + kk]);
        a0.x += v0.x; a0.y += v0.y; a0.z += v0.z; a0.w += v0.w;
        a1.x += v1.x; a1.y += v1.y; a1.z += v1.z; a1.w += v1.w;
    }
    while (e < end) {                         // uniform loop, predicated load
        if (e + half < end) {
            int s = __ldg(&g_col[e + half]);
            float4 v = __ldg(&y4[(size_t)s * 16 + kk]);
            a0.x += v.x; a0.y += v.y; a0.z += v.z; a0.w += v.w;
        }
        e += 2;
    }
    a0.x += a1.x; a0.y += a1.y; a0.z += a1.z; a0.w += a1.w;
    // cross-half reduction (all lanes participate)
    a0.x += __shfl_xor_sync(0xffffffffu, a0.x, 16);
    a0.y += __shfl_xor_sync(0xffffffffu, a0.y, 16);
    a0.z += __shfl_xor_sync(0xffffffffu, a0.z, 16);
    a0.w += __shfl_xor_sync(0xffffffffu, a0.w, 16);

    if (lane < 16) {
        float4 rv = __ldg(&((const float4*)g_r)[(size_t)w * 16 + kk]);
        float4 o;
        o.x = fmaxf(a0.x + rv.x, 0.f);
        o.y = fmaxf(a0.y + rv.y, 0.f);
        o.z = fmaxf(a0.z + rv.z, 0.f);
        o.w = fmaxf(a0.w + rv.w, 0.f);
        if (EMIT_F32)
            ((float4*)g_h)[(size_t)w * 16 + kk] = o;
        if (EMIT_SPLIT) {
            uint32_t lo0, lo1;
            uint32_t hi0 = pack_hi(o.x, o.y, lo0);
            uint32_t hi1 = pack_hi(o.z, o.w, lo1);
            *(uint2*)&g_hh[(size_t)w * 32 + 2 * kk] = make_uint2(hi0, hi1);
            *(uint2*)&g_hl[(size_t)w * 32 + 2 * kk] = make_uint2(lo0, lo1);
        }
    }
}

// ---------------- pooling ---------------------------------------------------
__global__ void k_pool(const int* __restrict__ batch) {
    int chunk = (blockIdx.x * blockDim.x + threadIdx.x) >> 5;
    int lane = threadIdx.x & 31;
    int n0 = chunk * 32;
    if (n0 >= N_NODES) return;
    int n1 = min(n0 + 32, N_NODES);
    int f = g_flags[1];
    const float2* h2 = (const float2*)g_h;
    float2 acc = make_float2(0.f, 0.f);
    int cnt = 0;
    int cur = f ? batch[2 * n0] : batch[n0];
    for (int n = n0; n < n1; n++) {
        int g = f ? batch[2 * n] : batch[n];
        if (g != cur) {
            atomicAdd(&g_pool[cur * 64 + 2 * lane], acc.x);
            atomicAdd(&g_pool[cur * 64 + 2 * lane + 1], acc.y);
            if (lane == 0) atomicAdd(&g_cnt[cur], (float)cnt);
            acc = make_float2(0.f, 0.f); cnt = 0; cur = g;
        }
        float2 v = h2[(size_t)n * 32 + lane];
        acc.x += v.x; acc.y += v.y; cnt++;
    }
    atomicAdd(&g_pool[cur * 64 + 2 * lane], acc.x);
    atomicAdd(&g_pool[cur * 64 + 2 * lane + 1], acc.y);
    if (lane == 0) atomicAdd(&g_cnt[cur], (float)cnt);
}

// ---------------- head ------------------------------------------------------
__global__ void k_head(const float* __restrict__ w1, const float* __restrict__ b1,
                       const float* __restrict__ w2, const float* __restrict__ b2,
                       float* __restrict__ out) {
    __shared__ float s_w1[64 * 64], s_b1[64], s_w2[128], s_b2[2];
    int t = threadIdx.x;
    for (int i = t; i < 64 * 64; i += 64) s_w1[i] = w1[i];
    s_b1[t] = b1[t];
    for (int i = t; i < 128; i += 64) s_w2[i] = w2[i];
    if (t < 2) s_b2[t] = b2[t];
    __syncthreads();

    float cnt = fmaxf(g_cnt[t], 1.f);
    float m[64];
#pragma unroll
    for (int c = 0; c < 64; c++) m[c] = g_pool[t * 64 + c] / cnt;

    float o0 = s_b2[0], o1 = s_b2[1];
    for (int j = 0; j < 64; j++) {
        float z = s_b1[j];
#pragma unroll 8
        for (int k = 0; k < 64; k++) z += m[k] * s_w1[k * 64 + j];
        z = fmaxf(z, 0.f);
        o0 += z * s_w2[j * 2];
        o1 += z * s_w2[j * 2 + 1];
    }
    out[t * 2 + 0] = o0;
    out[t * 2 + 1] = o1;
}

// ---------------- launch ----------------------------------------------------
extern "C" void kernel_launch(void* const* d_in, const int* in_sizes, int n_in,
                              void* d_out, int out_size) {
    const float* x       = (const float*)d_in[0];
    const int*   edge    = (const int*)d_in[1];
    const int*   batch   = (const int*)d_in[2];
    const float* w_rel0  = (const float*)d_in[3];
    const float* b_rel0  = (const float*)d_in[4];
    const float* w_root0 = (const float*)d_in[5];
    const float* w_rel1  = (const float*)d_in[6];
    const float* b_rel1  = (const float*)d_in[7];
    const float* w_root1 = (const float*)d_in[8];
    const float* w_rel2  = (const float*)d_in[9];
    const float* b_rel2  = (const float*)d_in[10];
    const float* w_root2 = (const float*)d_in[11];
    const float* head_w1 = (const float*)d_in[12];
    const float* head_b1 = (const float*)d_in[13];
    const float* head_w2 = (const float*)d_in[14];
    const float* head_b2 = (const float*)d_in[15];
    float* out = (float*)d_out;

    const int E = in_sizes[1] / 2;

    // stage smem: 2*A(64x72) + 2*B(128x72) bf16 + bias
    const int smem_stage = 2 * (64 * 72 * 2) + 2 * (128 * 72 * 2) + 256;   // 55552
    cudaFuncSetAttribute((const void*)k_hgemm<2, false>,
                         cudaFuncAttributeMaxDynamicSharedMemorySize, smem_stage);
    cudaFuncSetAttribute((const void*)k_hgemm<1, true>,
                         cudaFuncAttributeMaxDynamicSharedMemorySize, smem_stage);

    void *p_hh, *p_hl, *p_bh0, *p_bl0, *p_bh1, *p_bl1, *p_bh2, *p_bl2;
    cudaGetSymbolAddress(&p_hh, g_hh);
    cudaGetSymbolAddress(&p_hl, g_hl);
    cudaGetSymbolAddress(&p_bh0, g_bh0);
    cudaGetSymbolAddress(&p_bl0, g_bl0);
    cudaGetSymbolAddress(&p_bh1, g_bh1);
    cudaGetSymbolAddress(&p_bl1, g_bl1);
    cudaGetSymbolAddress(&p_bh2, g_bh2);
    cudaGetSymbolAddress(&p_bl2, g_bl2);

    const int gblk = (N_NODES + 63) / 64;   // 1563
    const int ablk = (N_NODES + 7) / 8;

    // one-time weight splits (single launch for all 3 layers)
    k_bsplit_all<<<(128 * 128 + 2 * 128 * 64 + 255) / 256, 256>>>(
        w_rel0, w_root0, w_rel1, w_root1, w_rel2, w_root2,
        (uint16_t*)p_bh0, (uint16_t*)p_bl0, (uint16_t*)p_bh1, (uint16_t*)p_bl1,
        (uint16_t*)p_bh2, (uint16_t*)p_bl2);

    // layer-0 GEMM (independent of CSR build)
    k_hgemm<2, false><<<gblk, 256, smem_stage>>>(x, nullptr, nullptr,
                                                 (const uint16_t*)p_bh0, (const uint16_t*)p_bl0, b_rel0);

    // CSR build
    k_init<<<(N_NODES + 255) / 256, 256>>>(edge, batch);
    k_hist<<<1024, 256>>>(edge, E);
    k_scan1<<<NSCAN_BLK, 1024>>>();
    k_scan2<<<1, 128>>>(NSCAN_BLK, E);
    k_scan3<<<NSCAN_BLK, 1024>>>();
    k_scatter<<<1024, 256>>>(edge, E);

    // layer 0 aggregate, then layers 1 & 2
    k_agg<true, false><<<ablk, 256>>>();
    k_hgemm<1, true><<<gblk, 256, smem_stage>>>(nullptr, (const uint32_t*)p_hh, (const uint32_t*)p_hl,
                                                (const uint16_t*)p_bh1, (const uint16_t*)p_bl1, b_rel1);
    k_agg<true, false><<<ablk, 256>>>();
    k_hgemm<1, true><<<gblk, 256, smem_stage>>>(nullptr, (const uint32_t*)p_hh, (const uint32_t*)p_hl,
                                                (const uint16_t*)p_bh2, (const uint16_t*)p_bl2, b_rel2);
    k_agg<false, true><<<ablk, 256>>>();

    // pooling + head
    k_pool<<<(N_NODES / 32 * 32 + 255) / 256, 256>>>(batch);
    k_head<<<1, 64>>>(head_w1, head_b1, head_w2, head_b2, out);
}

// round 12
// speedup vs baseline: 1.6106x; 1.0339x over previous
#include <cuda_runtime.h>
#include <cuda_bf16.h>
#include <cuda_fp16.h>
#include <cstdint>

#define N_NODES 100000
#define N_GRAPHS 64
#define HID 64
#define MAX_E 1600000
#define NSCAN_BLK 98   // ceil(100000/1024)

// ---------------- scratch (static device globals; no runtime alloc) --------
__device__ int   g_deg[N_NODES];
__device__ int   g_rowptr[N_NODES + 1];
__device__ int   g_tmp[N_NODES];
__device__ int   g_col[MAX_E];
__device__ uint32_t g_y16[N_NODES * 32];       // y in fp16 (half2 packed) — gather table
__device__ float g_r[N_NODES * HID];
__device__ float g_h[N_NODES * HID];
__device__ uint32_t g_hh[N_NODES * HID / 2];   // h split-bf16 hi (bf16x2 packed)
__device__ uint32_t g_hl[N_NODES * HID / 2];   // h split-bf16 lo
__device__ uint16_t g_bh0[128 * 128], g_bl0[128 * 128];
__device__ uint16_t g_bh1[128 * 64],  g_bl1[128 * 64];
__device__ uint16_t g_bh2[128 * 64],  g_bl2[128 * 64];
__device__ int   g_bsum[256];
__device__ int   g_boff[256];
__device__ float g_pool[N_GRAPHS * HID];
__device__ float g_cnt[N_GRAPHS];
__device__ int   g_flags[2];

// ---------------- init: dtype detect + zero deg/pool (merged) ---------------
__global__ void k_init(const int* __restrict__ edge, const int* __restrict__ batch) {
    int i = blockIdx.x * blockDim.x + threadIdx.x;
    if (i < N_NODES) g_deg[i] = 0;
    if (i < N_GRAPHS * HID) g_pool[i] = 0.f;
    if (i < N_GRAPHS) g_cnt[i] = 0.f;
    if (blockIdx.x < 2) {
        __shared__ int s_nz;
        int t = threadIdx.x;
        if (t == 0) s_nz = 0;
        __syncthreads();
        int v;
        if (blockIdx.x == 0) v = edge[2 * t + 1];
        else                 v = batch[2 * (30000 + t * 64) + 1];
        if (v != 0) atomicOr(&s_nz, 1);
        __syncthreads();
        if (t == 0) g_flags[blockIdx.x] = (s_nz == 0) ? 1 : 0;
    }
}

// ---------------- CSR build -------------------------------------------------
__global__ void k_hist(const int* __restrict__ edge, int E) {
    int f = g_flags[0];
    int stride = gridDim.x * blockDim.x;
    for (int e = blockIdx.x * blockDim.x + threadIdx.x; e < E; e += stride) {
        int d = f ? edge[2 * (E + e)] : edge[E + e];
        atomicAdd(&g_deg[d], 1);
    }
}
__global__ void k_scan1() {
    __shared__ int sm[1024];
    int i = blockIdx.x * 1024 + threadIdx.x;
    int v = (i < N_NODES) ? g_deg[i] : 0;
    sm[threadIdx.x] = v;
    __syncthreads();
    for (int off = 1; off < 1024; off <<= 1) {
        int u = (threadIdx.x >= off) ? sm[threadIdx.x - off] : 0;
        __syncthreads();
        sm[threadIdx.x] += u;
        __syncthreads();
    }
    if (i < N_NODES) g_tmp[i] = sm[threadIdx.x];
    if (threadIdx.x == 1023) g_bsum[blockIdx.x] = sm[1023];
}
__global__ void k_scan2(int nb, int E) {
    __shared__ int sm[128];
    int t = threadIdx.x;
    int v = (t < nb) ? g_bsum[t] : 0;
    sm[t] = v;
    __syncthreads();
    for (int off = 1; off < 128; off <<= 1) {
        int u = (t >= off) ? sm[t - off] : 0;
        __syncthreads();
        sm[t] += u;
        __syncthreads();
    }
    if (t < nb) g_boff[t] = sm[t] - v;
    if (t == 0) { g_rowptr[0] = 0; g_rowptr[N_NODES] = E; }
}
// scan3 + cursor merged: rowptr[i+1] = incl[i]+boff; tmp[i] = rowptr[i] (exclusive)
__global__ void k_scan3() {
    int i = blockIdx.x * 1024 + threadIdx.x;
    if (i < N_NODES) {
        int incl = g_tmp[i] + g_boff[blockIdx.x];
        g_rowptr[i + 1] = incl;
        g_tmp[i] = incl - g_deg[i];
    }
}
__global__ void k_scatter(const int* __restrict__ edge, int E) {
    int f = g_flags[0];
    int stride = gridDim.x * blockDim.x;
    for (int e = blockIdx.x * blockDim.x + threadIdx.x; e < E; e += stride) {
        int s = f ? edge[2 * e] : edge[e];
        int d = f ? edge[2 * (E + e)] : edge[E + e];
        int pos = atomicAdd(&g_tmp[d], 1);
        g_col[pos] = s;
    }
}

// ================= HMMA helpers (plain sm_80+ PTX) =========================
__device__ __forceinline__ uint32_t smem_u32(const void* p) {
    uint32_t a;
    asm("{ .reg .u64 t; cvta.to.shared.u64 t, %1; cvt.u32.u64 %0, t; }" : "=r"(a) : "l"(p));
    return a;
}
__device__ __forceinline__ void ldmx4(uint32_t& r0, uint32_t& r1, uint32_t& r2, uint32_t& r3,
                                      uint32_t addr) {
    asm volatile("ldmatrix.sync.aligned.m8n8.x4.shared.b16 {%0,%1,%2,%3}, [%4];"
                 : "=r"(r0), "=r"(r1), "=r"(r2), "=r"(r3) : "r"(addr));
}
__device__ __forceinline__ void mma16816(float* c, const uint32_t* a, uint32_t b0, uint32_t b1) {
    asm volatile("mma.sync.aligned.m16n8k16.row.col.f32.bf16.bf16.f32 "
                 "{%0,%1,%2,%3}, {%4,%5,%6,%7}, {%8,%9}, {%0,%1,%2,%3};"
                 : "+f"(c[0]), "+f"(c[1]), "+f"(c[2]), "+f"(c[3])
                 : "r"(a[0]), "r"(a[1]), "r"(a[2]), "r"(a[3]), "r"(b0), "r"(b1));
}
__device__ __forceinline__ uint32_t pack_hi(float x, float y, uint32_t& lo) {
    __nv_bfloat16 hx = __float2bfloat16(x);
    __nv_bfloat16 hy = __float2bfloat16(y);
    __nv_bfloat16 lx = __float2bfloat16(x - __bfloat162float(hx));
    __nv_bfloat16 ly = __float2bfloat16(y - __bfloat162float(hy));
    __nv_bfloat162 l2 = make_bfloat162(lx, ly);
    __nv_bfloat162 h2 = make_bfloat162(hx, hy);
    lo = *(uint32_t*)&l2;
    return *(uint32_t*)&h2;
}

// ---------------- one-time weight splits (all 3 layers in one launch) -------
__global__ void k_bsplit_all(const float* __restrict__ Wrel0, const float* __restrict__ Wroot0,
                             const float* __restrict__ Wrel1, const float* __restrict__ Wroot1,
                             const float* __restrict__ Wrel2, const float* __restrict__ Wroot2,
                             uint16_t* __restrict__ bh0, uint16_t* __restrict__ bl0,
                             uint16_t* __restrict__ bh1, uint16_t* __restrict__ bl1,
                             uint16_t* __restrict__ bh2, uint16_t* __restrict__ bl2) {
    int idx = blockIdx.x * blockDim.x + threadIdx.x;
    const float* Wrel; const float* Wroot; uint16_t* bh; uint16_t* bl; int KD;
    if (idx < 128 * 128) {
        Wrel = Wrel0; Wroot = Wroot0; bh = bh0; bl = bl0; KD = 128;
    } else if (idx < 128 * 128 + 128 * 64) {
        idx -= 128 * 128;
        Wrel = Wrel1; Wroot = Wroot1; bh = bh1; bl = bl1; KD = 64;
    } else if (idx < 128 * 128 + 2 * 128 * 64) {
        idx -= 128 * 128 + 128 * 64;
        Wrel = Wrel2; Wroot = Wroot2; bh = bh2; bl = bl2; KD = 64;
    } else return;
    int k = idx >> 7, n = idx & 127;
    float v = (n < 64) ? Wrel[k * 64 + n] : Wroot[k * 64 + (n - 64)];
    __nv_bfloat16 h = __float2bfloat16(v);
    __nv_bfloat16 l = __float2bfloat16(v - __bfloat162float(h));
    bh[n * KD + k] = *(uint16_t*)&h;
    bl[n * KD + k] = *(uint16_t*)&l;
}

// =============== tensor-core fused GEMM: y = A@Wrel ; r = A@Wroot + b =======
// Split-bf16, acc = AhBh + AhBl + AlBh in fp32 (mma.sync m16n8k16).
// Block tile: 64 rows x 128 out-cols. 256 threads = 8 warps (2m x 4n).
// y (cols 0..63) stored as fp16 half2 -> halves agg gather traffic.
template <int CHUNKS, bool SPLITA>
__global__ __launch_bounds__(256) void k_hgemm(const float* __restrict__ A,
                                               const uint32_t* __restrict__ Ahh,
                                               const uint32_t* __restrict__ All,
                                               const uint16_t* __restrict__ Bh,
                                               const uint16_t* __restrict__ Bl,
                                               const float* __restrict__ bias) {
    extern __shared__ char smem[];
    constexpr int KD = CHUNKS * 64;                  // logical K
    constexpr int SA = 64 + 8;                       // padded stage row stride (bf16)
    constexpr int ABYTES = 64 * SA * 2;
    constexpr int BBYTES = 128 * SA * 2;
    char* a_hi = smem;
    char* a_lo = smem + ABYTES;
    char* b_hi = smem + 2 * ABYTES;
    char* b_lo = smem + 2 * ABYTES + BBYTES;
    float* bsh = (float*)(smem + 2 * ABYTES + 2 * BBYTES);

    const int t = threadIdx.x;
    const int wid = t >> 5;
    const int lane = t & 31;
    const int row0 = blockIdx.x * 64;

    if (t < 64) bsh[t] = bias[t];

    const int m_base = (wid & 1) * 32;
    const int n_base = (wid >> 1) * 32;

    float c[8][4];
#pragma unroll
    for (int f = 0; f < 8; f++)
#pragma unroll
        for (int i = 0; i < 4; i++) c[f][i] = 0.f;

    const uint32_t sa_hi = smem_u32(a_hi), sa_lo = smem_u32(a_lo);
    const uint32_t sb_hi = smem_u32(b_hi), sb_lo = smem_u32(b_lo);

    const int a_row = (lane & 15);
    const int a_kof = (lane >> 4) * 8;
    const int b_row = ((lane >> 4) & 1) * 8 + (lane & 7);
    const int b_kof = ((lane >> 3) & 1) * 8;

#pragma unroll
    for (int chunk = 0; chunk < CHUNKS; chunk++) {
        if (chunk > 0) __syncthreads();   // smem stage reuse barrier

        // ---- A stage: 64 rows x 64 k-cols ----
        if (SPLITA) {
            for (int g = t; g < 64 * 8; g += 256) {
                int row = g >> 3;
                int j = g & 7;
                uint4 vh = make_uint4(0, 0, 0, 0), vl = make_uint4(0, 0, 0, 0);
                if (row0 + row < N_NODES) {
                    size_t gi = (size_t)(row0 + row) * 8 + j;
                    vh = ((const uint4*)Ahh)[gi];
                    vl = ((const uint4*)All)[gi];
                }
                uint32_t off = (uint32_t)(row * SA + j * 8) * 2;
                *(uint4*)(a_hi + off) = vh;
                *(uint4*)(a_lo + off) = vl;
            }
        } else {
            for (int g = t; g < 64 * 16; g += 256) {
                int row = g >> 4;
                int k4 = (g & 15) * 4;
                float4 v = make_float4(0.f, 0.f, 0.f, 0.f);
                if (row0 + row < N_NODES)
                    v = *(const float4*)(A + (size_t)(row0 + row) * KD + chunk * 64 + k4);
                uint32_t l01, l23;
                uint32_t h01 = pack_hi(v.x, v.y, l01);
                uint32_t h23 = pack_hi(v.z, v.w, l23);
                uint32_t off = (uint32_t)(row * SA + k4) * 2;
                *(uint2*)(a_hi + off) = make_uint2(h01, h23);
                *(uint2*)(a_lo + off) = make_uint2(l01, l23);
            }
        }
        // ---- B stage: 128 n-rows x 64 k-cols (coalesced copy of pre-split) --
        {
            for (int g = t; g < 128 * 8; g += 256) {
                int n = g >> 3;
                int j = g & 7;
                size_t gi = (size_t)n * (KD / 8) + chunk * 8 + j;
                uint32_t off = (uint32_t)(n * SA + j * 8) * 2;
                *(uint4*)(b_hi + off) = ((const uint4*)Bh)[gi];
                *(uint4*)(b_lo + off) = ((const uint4*)Bl)[gi];
            }
        }
        __syncthreads();

#pragma unroll
        for (int ks = 0; ks < 64; ks += 16) {
            uint32_t ah[2][4], al[2][4];
#pragma unroll
            for (int mi = 0; mi < 2; mi++) {
                uint32_t off = (uint32_t)((m_base + mi * 16 + a_row) * SA + ks + a_kof) * 2;
                ldmx4(ah[mi][0], ah[mi][1], ah[mi][2], ah[mi][3], sa_hi + off);
                ldmx4(al[mi][0], al[mi][1], al[mi][2], al[mi][3], sa_lo + off);
            }
            uint32_t bh[4][2], bl[4][2];
#pragma unroll
            for (int nj = 0; nj < 2; nj++) {
                uint32_t off = (uint32_t)((n_base + nj * 16 + b_row) * SA + ks + b_kof) * 2;
                uint32_t r0, r1, r2, r3;
                ldmx4(r0, r1, r2, r3, sb_hi + off);
                bh[nj * 2][0] = r0; bh[nj * 2][1] = r1;
                bh[nj * 2 + 1][0] = r2; bh[nj * 2 + 1][1] = r3;
                ldmx4(r0, r1, r2, r3, sb_lo + off);
                bl[nj * 2][0] = r0; bl[nj * 2][1] = r1;
                bl[nj * 2 + 1][0] = r2; bl[nj * 2 + 1][1] = r3;
            }
#pragma unroll
            for (int mi = 0; mi < 2; mi++)
#pragma unroll
                for (int ni = 0; ni < 4; ni++) {
                    float* cf = c[mi * 4 + ni];
                    mma16816(cf, ah[mi], bh[ni][0], bh[ni][1]);
                    mma16816(cf, ah[mi], bl[ni][0], bl[ni][1]);
                    mma16816(cf, al[mi], bh[ni][0], bh[ni][1]);
                }
        }
    }

    // ---- epilogue: y -> fp16 half2, r -> fp32 + bias ----
    const int er = lane >> 2;
    const int ec = (lane & 3) * 2;
#pragma unroll
    for (int mi = 0; mi < 2; mi++) {
#pragma unroll
        for (int half = 0; half < 2; half++) {
            int m = m_base + mi * 16 + half * 8 + er;
            int node = row0 + m;
            if (node >= N_NODES) continue;
#pragma unroll
            for (int ni = 0; ni < 4; ni++) {
                int j = n_base + ni * 8 + ec;
                float v0 = c[mi * 4 + ni][half * 2 + 0];
                float v1 = c[mi * 4 + ni][half * 2 + 1];
                if (j < 64) {
                    __half2 p = __floats2half2_rn(v0, v1);
                    g_y16[(size_t)node * 32 + (j >> 1)] = *(uint32_t*)&p;
                } else {
                    *(float2*)(g_r + (size_t)node * 64 + (j - 64)) =
                        make_float2(v0 + bsh[j - 64], v1 + bsh[j - 63]);
                }
            }
        }
    }
}

// ---------------- aggregation: h = relu(sum_{s->i} y[s] + r[i]) -------------
// Half-warp per edge; each lane loads 4 fp16 channels (uint2) and accumulates
// in fp32. EMIT_SPLIT: write split-bf16 h; EMIT_F32: write fp32 h.
template <bool EMIT_SPLIT, bool EMIT_F32>
__global__ void k_agg() {
    int w = (blockIdx.x * blockDim.x + threadIdx.x) >> 5;
    if (w >= N_NODES) return;                 // uniform per warp
    const int lane = threadIdx.x & 31;
    const int half = lane >> 4;               // which edge of the pair
    const int kk = lane & 15;                 // 4-channel group
    const int beg = g_rowptr[w];
    const int end = g_rowptr[w + 1];
    const uint2* y2 = (const uint2*)g_y16;    // 16 uint2 per node row

    float4 a0 = make_float4(0.f, 0.f, 0.f, 0.f);
    float4 a1 = make_float4(0.f, 0.f, 0.f, 0.f);
    int e = beg;
    for (; e + 3 < end; e += 4) {
        int s0 = __ldg(&g_col[e + half]);
        int s1 = __ldg(&g_col[e + 2 + half]);
        uint2 u0 = __ldg(&y2[(size_t)s0 * 16 + kk]);
        uint2 u1 = __ldg(&y2[(size_t)s1 * 16 + kk]);
        float2 f00 = __half22float2(*(__half2*)&u0.x);
        float2 f01 = __half22float2(*(__half2*)&u0.y);
        float2 f10 = __half22float2(*(__half2*)&u1.x);
        float2 f11 = __half22float2(*(__half2*)&u1.y);
        a0.x += f00.x; a0.y += f00.y; a0.z += f01.x; a0.w += f01.y;
        a1.x += f10.x; a1.y += f10.y; a1.z += f11.x; a1.w += f11.y;
    }
    while (e < end) {                         // uniform loop, predicated load
        if (e + half < end) {
            int s = __ldg(&g_col[e + half]);
            uint2 u = __ldg(&y2[(size_t)s * 16 + kk]);
            float2 f0 = __half22float2(*(__half2*)&u.x);
            float2 f1 = __half22float2(*(__half2*)&u.y);
            a0.x += f0.x; a0.y += f0.y; a0.z += f1.x; a0.w += f1.y;
        }
        e += 2;
    }
    a0.x += a1.x; a0.y += a1.y; a0.z += a1.z; a0.w += a1.w;
    // cross-half reduction (all lanes participate)
    a0.x += __shfl_xor_sync(0xffffffffu, a0.x, 16);
    a0.y += __shfl_xor_sync(0xffffffffu, a0.y, 16);
    a0.z += __shfl_xor_sync(0xffffffffu, a0.z, 16);
    a0.w += __shfl_xor_sync(0xffffffffu, a0.w, 16);

    if (lane < 16) {
        float4 rv = __ldg(&((const float4*)g_r)[(size_t)w * 16 + kk]);
        float4 o;
        o.x = fmaxf(a0.x + rv.x, 0.f);
        o.y = fmaxf(a0.y + rv.y, 0.f);
        o.z = fmaxf(a0.z + rv.z, 0.f);
        o.w = fmaxf(a0.w + rv.w, 0.f);
        if (EMIT_F32)
            ((float4*)g_h)[(size_t)w * 16 + kk] = o;
        if (EMIT_SPLIT) {
            uint32_t lo0, lo1;
            uint32_t hi0 = pack_hi(o.x, o.y, lo0);
            uint32_t hi1 = pack_hi(o.z, o.w, lo1);
            *(uint2*)&g_hh[(size_t)w * 32 + 2 * kk] = make_uint2(hi0, hi1);
            *(uint2*)&g_hl[(size_t)w * 32 + 2 * kk] = make_uint2(lo0, lo1);
        }
    }
}

// ---------------- pooling ---------------------------------------------------
__global__ void k_pool(const int* __restrict__ batch) {
    int chunk = (blockIdx.x * blockDim.x + threadIdx.x) >> 5;
    int lane = threadIdx.x & 31;
    int n0 = chunk * 32;
    if (n0 >= N_NODES) return;
    int n1 = min(n0 + 32, N_NODES);
    int f = g_flags[1];
    const float2* h2 = (const float2*)g_h;
    float2 acc = make_float2(0.f, 0.f);
    int cnt = 0;
    int cur = f ? batch[2 * n0] : batch[n0];
    for (int n = n0; n < n1; n++) {
        int g = f ? batch[2 * n] : batch[n];
        if (g != cur) {
            atomicAdd(&g_pool[cur * 64 + 2 * lane], acc.x);
            atomicAdd(&g_pool[cur * 64 + 2 * lane + 1], acc.y);
            if (lane == 0) atomicAdd(&g_cnt[cur], (float)cnt);
            acc = make_float2(0.f, 0.f); cnt = 0; cur = g;
        }
        float2 v = h2[(size_t)n * 32 + lane];
        acc.x += v.x; acc.y += v.y; cnt++;
    }
    atomicAdd(&g_pool[cur * 64 + 2 * lane], acc.x);
    atomicAdd(&g_pool[cur * 64 + 2 * lane + 1], acc.y);
    if (lane == 0) atomicAdd(&g_cnt[cur], (float)cnt);
}

// ---------------- head ------------------------------------------------------
__global__ void k_head(const float* __restrict__ w1, const float* __restrict__ b1,
                       const float* __restrict__ w2, const float* __restrict__ b2,
                       float* __restrict__ out) {
    __shared__ float s_w1[64 * 64], s_b1[64], s_w2[128], s_b2[2];
    int t = threadIdx.x;
    for (int i = t; i < 64 * 64; i += 64) s_w1[i] = w1[i];
    s_b1[t] = b1[t];
    for (int i = t; i < 128; i += 64) s_w2[i] = w2[i];
    if (t < 2) s_b2[t] = b2[t];
    __syncthreads();

    float cnt = fmaxf(g_cnt[t], 1.f);
    float m[64];
#pragma unroll
    for (int c = 0; c < 64; c++) m[c] = g_pool[t * 64 + c] / cnt;

    float o0 = s_b2[0], o1 = s_b2[1];
    for (int j = 0; j < 64; j++) {
        float z = s_b1[j];
#pragma unroll 8
        for (int k = 0; k < 64; k++) z += m[k] * s_w1[k * 64 + j];
        z = fmaxf(z, 0.f);
        o0 += z * s_w2[j * 2];
        o1 += z * s_w2[j * 2 + 1];
    }
    out[t * 2 + 0] = o0;
    out[t * 2 + 1] = o1;
}

// ---------------- launch ----------------------------------------------------
extern "C" void kernel_launch(void* const* d_in, const int* in_sizes, int n_in,
                              void* d_out, int out_size) {
    const float* x       = (const float*)d_in[0];
    const int*   edge    = (const int*)d_in[1];
    const int*   batch   = (const int*)d_in[2];
    const float* w_rel0  = (const float*)d_in[3];
    const float* b_rel0  = (const float*)d_in[4];
    const float* w_root0 = (const float*)d_in[5];
    const float* w_rel1  = (const float*)d_in[6];
    const float* b_rel1  = (const float*)d_in[7];
    const float* w_root1 = (const float*)d_in[8];
    const float* w_rel2  = (const float*)d_in[9];
    const float* b_rel2  = (const float*)d_in[10];
    const float* w_root2 = (const float*)d_in[11];
    const float* head_w1 = (const float*)d_in[12];
    const float* head_b1 = (const float*)d_in[13];
    const float* head_w2 = (const float*)d_in[14];
    const float* head_b2 = (const float*)d_in[15];
    float* out = (float*)d_out;

    const int E = in_sizes[1] / 2;

    // stage smem: 2*A(64x72) + 2*B(128x72) bf16 + bias
    const int smem_stage = 2 * (64 * 72 * 2) + 2 * (128 * 72 * 2) + 256;   // 55552
    cudaFuncSetAttribute((const void*)k_hgemm<2, false>,
                         cudaFuncAttributeMaxDynamicSharedMemorySize, smem_stage);
    cudaFuncSetAttribute((const void*)k_hgemm<1, true>,
                         cudaFuncAttributeMaxDynamicSharedMemorySize, smem_stage);

    void *p_hh, *p_hl, *p_bh0, *p_bl0, *p_bh1, *p_bl1, *p_bh2, *p_bl2;
    cudaGetSymbolAddress(&p_hh, g_hh);
    cudaGetSymbolAddress(&p_hl, g_hl);
    cudaGetSymbolAddress(&p_bh0, g_bh0);
    cudaGetSymbolAddress(&p_bl0, g_bl0);
    cudaGetSymbolAddress(&p_bh1, g_bh1);
    cudaGetSymbolAddress(&p_bl1, g_bl1);
    cudaGetSymbolAddress(&p_bh2, g_bh2);
    cudaGetSymbolAddress(&p_bl2, g_bl2);

    const int gblk = (N_NODES + 63) / 64;   // 1563
    const int ablk = (N_NODES + 7) / 8;

    // one-time weight splits (single launch for all 3 layers)
    k_bsplit_all<<<(128 * 128 + 2 * 128 * 64 + 255) / 256, 256>>>(
        w_rel0, w_root0, w_rel1, w_root1, w_rel2, w_root2,
        (uint16_t*)p_bh0, (uint16_t*)p_bl0, (uint16_t*)p_bh1, (uint16_t*)p_bl1,
        (uint16_t*)p_bh2, (uint16_t*)p_bl2);

    // layer-0 GEMM (independent of CSR build)
    k_hgemm<2, false><<<gblk, 256, smem_stage>>>(x, nullptr, nullptr,
                                                 (const uint16_t*)p_bh0, (const uint16_t*)p_bl0, b_rel0);

    // CSR build
    k_init<<<(N_NODES + 255) / 256, 256>>>(edge, batch);
    k_hist<<<1024, 256>>>(edge, E);
    k_scan1<<<NSCAN_BLK, 1024>>>();
    k_scan2<<<1, 128>>>(NSCAN_BLK, E);
    k_scan3<<<NSCAN_BLK, 1024>>>();
    k_scatter<<<1024, 256>>>(edge, E);

    // layer 0 aggregate, then layers 1 & 2
    k_agg<true, false><<<ablk, 256>>>();
    k_hgemm<1, true><<<gblk, 256, smem_stage>>>(nullptr, (const uint32_t*)p_hh, (const uint32_t*)p_hl,
                                                (const uint16_t*)p_bh1, (const uint16_t*)p_bl1, b_rel1);
    k_agg<true, false><<<ablk, 256>>>();
    k_hgemm<1, true><<<gblk, 256, smem_stage>>>(nullptr, (const uint32_t*)p_hh, (const uint32_t*)p_hl,
                                                (const uint16_t*)p_bh2, (const uint16_t*)p_bl2, b_rel2);
    k_agg<false, true><<<ablk, 256>>>();

    // pooling + head
    k_pool<<<(N_NODES / 32 * 32 + 255) / 256, 256>>>(batch);
    k_head<<<1, 64>>>(head_w1, head_b1, head_w2, head_b2, out);
}

// round 14
// speedup vs baseline: 1.6591x; 1.0301x over previous
#include <cuda_runtime.h>
#include <cuda_bf16.h>
#include <cuda_fp16.h>
#include <cstdint>

#define N_NODES 100000
#define N_GRAPHS 64
#define HID 64
#define MAX_E 1600000
#define NSCAN_BLK 98    // ceil(100000/1024)
#define INIT_BLK 391    // ceil(100000/256)
#define BSPLIT_ELEMS (128 * 128 + 2 * 128 * 64)
#define BSPLIT_BLK ((BSPLIT_ELEMS + 255) / 256)

// ---------------- scratch (static device globals; no runtime alloc) --------
__device__ int   g_deg[N_NODES];
__device__ int   g_rowptr[N_NODES + 1];
__device__ int   g_tmp[N_NODES];
__device__ int   g_col[MAX_E];
__device__ uint32_t g_y16[N_NODES * 32];       // y in fp16 (half2 packed) — gather table
__device__ float g_r[N_NODES * HID];
__device__ float g_h[N_NODES * HID];
__device__ uint32_t g_hh[N_NODES * HID / 2];   // h bf16 (bf16x2 packed) — GEMM A input
__device__ uint16_t g_bh0[128 * 128], g_bl0[128 * 128];
__device__ uint16_t g_bh1[128 * 64],  g_bl1[128 * 64];
__device__ uint16_t g_bh2[128 * 64],  g_bl2[128 * 64];
__device__ int   g_bsum[256];
__device__ int   g_boff[256];
__device__ float g_pool[N_GRAPHS * HID];
__device__ float g_cnt[N_GRAPHS];
__device__ int   g_flags[2];

// ================= helpers ==================================================
__device__ __forceinline__ uint32_t smem_u32(const void* p) {
    uint32_t a;
    asm("{ .reg .u64 t; cvta.to.shared.u64 t, %1; cvt.u32.u64 %0, t; }" : "=r"(a) : "l"(p));
    return a;
}
__device__ __forceinline__ void ldmx4(uint32_t& r0, uint32_t& r1, uint32_t& r2, uint32_t& r3,
                                      uint32_t addr) {
    asm volatile("ldmatrix.sync.aligned.m8n8.x4.shared.b16 {%0,%1,%2,%3}, [%4];"
                 : "=r"(r0), "=r"(r1), "=r"(r2), "=r"(r3) : "r"(addr));
}
__device__ __forceinline__ void mma16816(float* c, const uint32_t* a, uint32_t b0, uint32_t b1) {
    asm volatile("mma.sync.aligned.m16n8k16.row.col.f32.bf16.bf16.f32 "
                 "{%0,%1,%2,%3}, {%4,%5,%6,%7}, {%8,%9}, {%0,%1,%2,%3};"
                 : "+f"(c[0]), "+f"(c[1]), "+f"(c[2]), "+f"(c[3])
                 : "r"(a[0]), "r"(a[1]), "r"(a[2]), "r"(a[3]), "r"(b0), "r"(b1));
}
__device__ __forceinline__ uint32_t pack_bf16x2(float x, float y) {
    __nv_bfloat162 h2 = make_bfloat162(__float2bfloat16(x), __float2bfloat16(y));
    return *(uint32_t*)&h2;
}

// ---------------- pre: init + detect + weight splits (one launch) -----------
__global__ void k_pre(const int* __restrict__ edge, const int* __restrict__ batch,
                      const float* __restrict__ Wrel0, const float* __restrict__ Wroot0,
                      const float* __restrict__ Wrel1, const float* __restrict__ Wroot1,
                      const float* __restrict__ Wrel2, const float* __restrict__ Wroot2,
                      uint16_t* __restrict__ bh0, uint16_t* __restrict__ bl0,
                      uint16_t* __restrict__ bh1, uint16_t* __restrict__ bl1,
                      uint16_t* __restrict__ bh2, uint16_t* __restrict__ bl2) {
    if (blockIdx.x < INIT_BLK) {
        int i = blockIdx.x * blockDim.x + threadIdx.x;
        if (i < N_NODES) g_deg[i] = 0;
        if (i < N_GRAPHS * HID) g_pool[i] = 0.f;
        if (i < N_GRAPHS) g_cnt[i] = 0.f;
        if (blockIdx.x < 2) {
            __shared__ int s_nz;
            int t = threadIdx.x;
            if (t == 0) s_nz = 0;
            __syncthreads();
            int v;
            if (blockIdx.x == 0) v = edge[2 * t + 1];
            else                 v = batch[2 * (30000 + t * 64) + 1];
            if (v != 0) atomicOr(&s_nz, 1);
            __syncthreads();
            if (t == 0) g_flags[blockIdx.x] = (s_nz == 0) ? 1 : 0;
        }
        return;
    }
    int idx = (blockIdx.x - INIT_BLK) * blockDim.x + threadIdx.x;
    const float* Wrel; const float* Wroot; uint16_t* bh; uint16_t* bl; int KD;
    if (idx < 128 * 128) {
        Wrel = Wrel0; Wroot = Wroot0; bh = bh0; bl = bl0; KD = 128;
    } else if (idx < 128 * 128 + 128 * 64) {
        idx -= 128 * 128;
        Wrel = Wrel1; Wroot = Wroot1; bh = bh1; bl = bl1; KD = 64;
    } else if (idx < 128 * 128 + 2 * 128 * 64) {
        idx -= 128 * 128 + 128 * 64;
        Wrel = Wrel2; Wroot = Wroot2; bh = bh2; bl = bl2; KD = 64;
    } else return;
    int k = idx >> 7, n = idx & 127;
    float v = (n < 64) ? Wrel[k * 64 + n] : Wroot[k * 64 + (n - 64)];
    __nv_bfloat16 h = __float2bfloat16(v);
    __nv_bfloat16 l = __float2bfloat16(v - __bfloat162float(h));
    bh[n * KD + k] = *(uint16_t*)&h;
    bl[n * KD + k] = *(uint16_t*)&l;
}

// ---------------- CSR build -------------------------------------------------
__global__ void k_hist(const int* __restrict__ edge, int E) {
    int f = g_flags[0];
    int stride = gridDim.x * blockDim.x;
    for (int e = blockIdx.x * blockDim.x + threadIdx.x; e < E; e += stride) {
        int d = f ? edge[2 * (E + e)] : edge[E + e];
        atomicAdd(&g_deg[d], 1);
    }
}
__global__ void k_scan1() {
    __shared__ int sm[1024];
    int i = blockIdx.x * 1024 + threadIdx.x;
    int v = (i < N_NODES) ? g_deg[i] : 0;
    sm[threadIdx.x] = v;
    __syncthreads();
    for (int off = 1; off < 1024; off <<= 1) {
        int u = (threadIdx.x >= off) ? sm[threadIdx.x - off] : 0;
        __syncthreads();
        sm[threadIdx.x] += u;
        __syncthreads();
    }
    if (i < N_NODES) g_tmp[i] = sm[threadIdx.x];
    if (threadIdx.x == 1023) g_bsum[blockIdx.x] = sm[1023];
}
__global__ void k_scan2(int nb, int E) {
    __shared__ int sm[128];
    int t = threadIdx.x;
    int v = (t < nb) ? g_bsum[t] : 0;
    sm[t] = v;
    __syncthreads();
    for (int off = 1; off < 128; off <<= 1) {
        int u = (t >= off) ? sm[t - off] : 0;
        __syncthreads();
        sm[t] += u;
        __syncthreads();
    }
    if (t < nb) g_boff[t] = sm[t] - v;
    if (t == 0) { g_rowptr[0] = 0; g_rowptr[N_NODES] = E; }
}
__global__ void k_scan3() {
    int i = blockIdx.x * 1024 + threadIdx.x;
    if (i < N_NODES) {
        int incl = g_tmp[i] + g_boff[blockIdx.x];
        g_rowptr[i + 1] = incl;
        g_tmp[i] = incl - g_deg[i];
    }
}
__global__ void k_scatter(const int* __restrict__ edge, int E) {
    int f = g_flags[0];
    int stride = gridDim.x * blockDim.x;
    for (int e = blockIdx.x * blockDim.x + threadIdx.x; e < E; e += stride) {
        int s = f ? edge[2 * e] : edge[e];
        int d = f ? edge[2 * (E + e)] : edge[E + e];
        int pos = atomicAdd(&g_tmp[d], 1);
        g_col[pos] = s;
    }
}

// =============== tensor-core fused GEMM: y = A@Wrel ; r = A@Wroot + b =======
// A single-bf16, B split hi/lo: acc = Ah*Bh + Ah*Bl (fp32, mma.sync m16n8k16).
// (B must stay split: its rounding error is shared across nodes and would not
//  average out in mean-pooling; A's error is node-independent and does.)
// Block tile: 64 rows x 128 out-cols. 256 threads = 8 warps (2m x 4n).
template <int CHUNKS, bool BF16A>
__global__ __launch_bounds__(256) void k_hgemm(const float* __restrict__ A,
                                               const uint32_t* __restrict__ Abf,
                                               const uint16_t* __restrict__ Bh,
                                               const uint16_t* __restrict__ Bl,
                                               const float* __restrict__ bias) {
    extern __shared__ char smem[];
    constexpr int KD = CHUNKS * 64;                  // logical K
    constexpr int SA = 64 + 8;                       // padded stage row stride (bf16)
    constexpr int ABYTES = 64 * SA * 2;
    constexpr int BBYTES = 128 * SA * 2;
    char* a_hi = smem;
    char* b_hi = smem + ABYTES;
    char* b_lo = smem + ABYTES + BBYTES;
    float* bsh = (float*)(smem + ABYTES + 2 * BBYTES);

    const int t = threadIdx.x;
    const int wid = t >> 5;
    const int lane = t & 31;
    const int row0 = blockIdx.x * 64;

    if (t < 64) bsh[t] = bias[t];

    const int m_base = (wid & 1) * 32;
    const int n_base = (wid >> 1) * 32;

    float c[8][4];
#pragma unroll
    for (int f = 0; f < 8; f++)
#pragma unroll
        for (int i = 0; i < 4; i++) c[f][i] = 0.f;

    const uint32_t sa_hi = smem_u32(a_hi);
    const uint32_t sb_hi = smem_u32(b_hi), sb_lo = smem_u32(b_lo);

    const int a_row = (lane & 15);
    const int a_kof = (lane >> 4) * 8;
    const int b_row = ((lane >> 4) & 1) * 8 + (lane & 7);
    const int b_kof = ((lane >> 3) & 1) * 8;

#pragma unroll
    for (int chunk = 0; chunk < CHUNKS; chunk++) {
        if (chunk > 0) __syncthreads();   // smem stage reuse barrier

        // ---- A stage: 64 rows x 64 k-cols (single bf16) ----
        if (BF16A) {
            for (int g = t; g < 64 * 8; g += 256) {
                int row = g >> 3;
                int j = g & 7;
                uint4 vh = make_uint4(0, 0, 0, 0);
                if (row0 + row < N_NODES)
                    vh = ((const uint4*)Abf)[(size_t)(row0 + row) * 8 + j];
                *(uint4*)(a_hi + (uint32_t)(row * SA + j * 8) * 2) = vh;
            }
        } else {
            for (int g = t; g < 64 * 16; g += 256) {
                int row = g >> 4;
                int k4 = (g & 15) * 4;
                float4 v = make_float4(0.f, 0.f, 0.f, 0.f);
                if (row0 + row < N_NODES)
                    v = *(const float4*)(A + (size_t)(row0 + row) * KD + chunk * 64 + k4);
                uint32_t h01 = pack_bf16x2(v.x, v.y);
                uint32_t h23 = pack_bf16x2(v.z, v.w);
                *(uint2*)(a_hi + (uint32_t)(row * SA + k4) * 2) = make_uint2(h01, h23);
            }
        }
        // ---- B stage: 128 n-rows x 64 k-cols (coalesced copy of pre-split) --
        {
            for (int g = t; g < 128 * 8; g += 256) {
                int n = g >> 3;
                int j = g & 7;
                size_t gi = (size_t)n * (KD / 8) + chunk * 8 + j;
                uint32_t off = (uint32_t)(n * SA + j * 8) * 2;
                *(uint4*)(b_hi + off) = ((const uint4*)Bh)[gi];
                *(uint4*)(b_lo + off) = ((const uint4*)Bl)[gi];
            }
        }
        __syncthreads();

#pragma unroll
        for (int ks = 0; ks < 64; ks += 16) {
            uint32_t ah[2][4];
#pragma unroll
            for (int mi = 0; mi < 2; mi++) {
                uint32_t off = (uint32_t)((m_base + mi * 16 + a_row) * SA + ks + a_kof) * 2;
                ldmx4(ah[mi][0], ah[mi][1], ah[mi][2], ah[mi][3], sa_hi + off);
            }
            uint32_t bh[4][2], bl[4][2];
#pragma unroll
            for (int nj = 0; nj < 2; nj++) {
                uint32_t off = (uint32_t)((n_base + nj * 16 + b_row) * SA + ks + b_kof) * 2;
                uint32_t r0, r1, r2, r3;
                ldmx4(r0, r1, r2, r3, sb_hi + off);
                bh[nj * 2][0] = r0; bh[nj * 2][1] = r1;
                bh[nj * 2 + 1][0] = r2; bh[nj * 2 + 1][1] = r3;
                ldmx4(r0, r1, r2, r3, sb_lo + off);
                bl[nj * 2][0] = r0; bl[nj * 2][1] = r1;
                bl[nj * 2 + 1][0] = r2; bl[nj * 2 + 1][1] = r3;
            }
#pragma unroll
            for (int mi = 0; mi < 2; mi++)
#pragma unroll
                for (int ni = 0; ni < 4; ni++) {
                    float* cf = c[mi * 4 + ni];
                    mma16816(cf, ah[mi], bh[ni][0], bh[ni][1]);
                    mma16816(cf, ah[mi], bl[ni][0], bl[ni][1]);
                }
        }
    }

    // ---- epilogue: y -> fp16 half2, r -> fp32 + bias ----
    const int er = lane >> 2;
    const int ec = (lane & 3) * 2;
#pragma unroll
    for (int mi = 0; mi < 2; mi++) {
#pragma unroll
        for (int half = 0; half < 2; half++) {
            int m = m_base + mi * 16 + half * 8 + er;
            int node = row0 + m;
            if (node >= N_NODES) continue;
#pragma unroll
            for (int ni = 0; ni < 4; ni++) {
                int j = n_base + ni * 8 + ec;
                float v0 = c[mi * 4 + ni][half * 2 + 0];
                float v1 = c[mi * 4 + ni][half * 2 + 1];
                if (j < 64) {
                    __half2 p = __floats2half2_rn(v0, v1);
                    g_y16[(size_t)node * 32 + (j >> 1)] = *(uint32_t*)&p;
                } else {
                    *(float2*)(g_r + (size_t)node * 64 + (j - 64)) =
                        make_float2(v0 + bsh[j - 64], v1 + bsh[j - 63]);
                }
            }
        }
    }
}

// ---------------- aggregation: h = relu(sum_{s->i} y[s] + r[i]) -------------
// Half-warp per edge; each lane loads 4 fp16 channels (uint2), fp32 accum.
// EMIT_BF16: write bf16 h (next layer's GEMM A); EMIT_F32: write fp32 h (pool).
template <bool EMIT_BF16, bool EMIT_F32>
__global__ void k_agg() {
    int w = (blockIdx.x * blockDim.x + threadIdx.x) >> 5;
    if (w >= N_NODES) return;                 // uniform per warp
    const int lane = threadIdx.x & 31;
    const int half = lane >> 4;               // which edge of the pair
    const int kk = lane & 15;                 // 4-channel group
    const int beg = g_rowptr[w];
    const int end = g_rowptr[w + 1];
    const uint2* y2 = (const uint2*)g_y16;    // 16 uint2 per node row

    float4 a0 = make_float4(0.f, 0.f, 0.f, 0.f);
    float4 a1 = make_float4(0.f, 0.f, 0.f, 0.f);
    int e = beg;
    for (; e + 3 < end; e += 4) {
        int s0 = __ldg(&g_col[e + half]);
        int s1 = __ldg(&g_col[e + 2 + half]);
        uint2 u0 = __ldg(&y2[(size_t)s0 * 16 + kk]);
        uint2 u1 = __ldg(&y2[(size_t)s1 * 16 + kk]);
        float2 f00 = __half22float2(*(__half2*)&u0.x);
        float2 f01 = __half22float2(*(__half2*)&u0.y);
        float2 f10 = __half22float2(*(__half2*)&u1.x);
        float2 f11 = __half22float2(*(__half2*)&u1.y);
        a0.x += f00.x; a0.y += f00.y; a0.z += f01.x; a0.w += f01.y;
        a1.x += f10.x; a1.y += f10.y; a1.z += f11.x; a1.w += f11.y;
    }
    while (e < end) {                         // uniform loop, predicated load
        if (e + half < end) {
            int s = __ldg(&g_col[e + half]);
            uint2 u = __ldg(&y2[(size_t)s * 16 + kk]);
            float2 f0 = __half22float2(*(__half2*)&u.x);
            float2 f1 = __half22float2(*(__half2*)&u.y);
            a0.x += f0.x; a0.y += f0.y; a0.z += f1.x; a0.w += f1.y;
        }
        e += 2;
    }
    a0.x += a1.x; a0.y += a1.y; a0.z += a1.z; a0.w += a1.w;
    a0.x += __shfl_xor_sync(0xffffffffu, a0.x, 16);
    a0.y += __shfl_xor_sync(0xffffffffu, a0.y, 16);
    a0.z += __shfl_xor_sync(0xffffffffu, a0.z, 16);
    a0.w += __shfl_xor_sync(0xffffffffu, a0.w, 16);

    if (lane < 16) {
        float4 rv = __ldg(&((const float4*)g_r)[(size_t)w * 16 + kk]);
        float4 o;
        o.x = fmaxf(a0.x + rv.x, 0.f);
        o.y = fmaxf(a0.y + rv.y, 0.f);
        o.z = fmaxf(a0.z + rv.z, 0.f);
        o.w = fmaxf(a0.w + rv.w, 0.f);
        if (EMIT_F32)
            ((float4*)g_h)[(size_t)w * 16 + kk] = o;
        if (EMIT_BF16)
            *(uint2*)&g_hh[(size_t)w * 32 + 2 * kk] =
                make_uint2(pack_bf16x2(o.x, o.y), pack_bf16x2(o.z, o.w));
    }
}

// ---------------- pooling ---------------------------------------------------
__global__ void k_pool(const int* __restrict__ batch) {
    int chunk = (blockIdx.x * blockDim.x + threadIdx.x) >> 5;
    int lane = threadIdx.x & 31;
    int n0 = chunk * 32;
    if (n0 >= N_NODES) return;
    int n1 = min(n0 + 32, N_NODES);
    int f = g_flags[1];
    const float2* h2 = (const float2*)g_h;
    float2 acc = make_float2(0.f, 0.f);
    int cnt = 0;
    int cur = f ? batch[2 * n0] : batch[n0];
    for (int n = n0; n < n1; n++) {
        int g = f ? batch[2 * n] : batch[n];
        if (g != cur) {
            atomicAdd(&g_pool[cur * 64 + 2 * lane], acc.x);
            atomicAdd(&g_pool[cur * 64 + 2 * lane + 1], acc.y);
            if (lane == 0) atomicAdd(&g_cnt[cur], (float)cnt);
            acc = make_float2(0.f, 0.f); cnt = 0; cur = g;
        }
        float2 v = h2[(size_t)n * 32 + lane];
        acc.x += v.x; acc.y += v.y; cnt++;
    }
    atomicAdd(&g_pool[cur * 64 + 2 * lane], acc.x);
    atomicAdd(&g_pool[cur * 64 + 2 * lane + 1], acc.y);
    if (lane == 0) atomicAdd(&g_cnt[cur], (float)cnt);
}

// ---------------- head ------------------------------------------------------
__global__ void k_head(const float* __restrict__ w1, const float* __restrict__ b1,
                       const float* __restrict__ w2, const float* __restrict__ b2,
                       float* __restrict__ out) {
    __shared__ float s_w1[64 * 64], s_b1[64], s_w2[128], s_b2[2];
    int t = threadIdx.x;
    for (int i = t; i < 64 * 64; i += 64) s_w1[i] = w1[i];
    s_b1[t] = b1[t];
    for (int i = t; i < 128; i += 64) s_w2[i] = w2[i];
    if (t < 2) s_b2[t] = b2[t];
    __syncthreads();

    float cnt = fmaxf(g_cnt[t], 1.f);
    float m[64];
#pragma unroll
    for (int c = 0; c < 64; c++) m[c] = g_pool[t * 64 + c] / cnt;

    float o0 = s_b2[0], o1 = s_b2[1];
    for (int j = 0; j < 64; j++) {
        float z = s_b1[j];
#pragma unroll 8
        for (int k = 0; k < 64; k++) z += m[k] * s_w1[k * 64 + j];
        z = fmaxf(z, 0.f);
        o0 += z * s_w2[j * 2];
        o1 += z * s_w2[j * 2 + 1];
    }
    out[t * 2 + 0] = o0;
    out[t * 2 + 1] = o1;
}

// ---------------- launch ----------------------------------------------------
extern "C" void kernel_launch(void* const* d_in, const int* in_sizes, int n_in,
                              void* d_out, int out_size) {
    const float* x       = (const float*)d_in[0];
    const int*   edge    = (const int*)d_in[1];
    const int*   batch   = (const int*)d_in[2];
    const float* w_rel0  = (const float*)d_in[3];
    const float* b_rel0  = (const float*)d_in[4];
    const float* w_root0 = (const float*)d_in[5];
    const float* w_rel1  = (const float*)d_in[6];
    const float* b_rel1  = (const float*)d_in[7];
    const float* w_root1 = (const float*)d_in[8];
    const float* w_rel2  = (const float*)d_in[9];
    const float* b_rel2  = (const float*)d_in[10];
    const float* w_root2 = (const float*)d_in[11];
    const float* head_w1 = (const float*)d_in[12];
    const float* head_b1 = (const float*)d_in[13];
    const float* head_w2 = (const float*)d_in[14];
    const float* head_b2 = (const float*)d_in[15];
    float* out = (float*)d_out;

    const int E = in_sizes[1] / 2;

    // stage smem: A(64x72) + 2*B(128x72) bf16 + bias
    const int smem_stage = (64 * 72 * 2) + 2 * (128 * 72 * 2) + 256;   // 46336
    cudaFuncSetAttribute((const void*)k_hgemm<2, false>,
                         cudaFuncAttributeMaxDynamicSharedMemorySize, smem_stage);
    cudaFuncSetAttribute((const void*)k_hgemm<1, true>,
                         cudaFuncAttributeMaxDynamicSharedMemorySize, smem_stage);

    void *p_hh, *p_bh0, *p_bl0, *p_bh1, *p_bl1, *p_bh2, *p_bl2;
    cudaGetSymbolAddress(&p_hh, g_hh);
    cudaGetSymbolAddress(&p_bh0, g_bh0);
    cudaGetSymbolAddress(&p_bl0, g_bl0);
    cudaGetSymbolAddress(&p_bh1, g_bh1);
    cudaGetSymbolAddress(&p_bl1, g_bl1);
    cudaGetSymbolAddress(&p_bh2, g_bh2);
    cudaGetSymbolAddress(&p_bl2, g_bl2);

    const int gblk = (N_NODES + 63) / 64;   // 1563
    const int ablk = (N_NODES + 7) / 8;

    // pre: init + detect + weight splits (one launch)
    k_pre<<<INIT_BLK + BSPLIT_BLK, 256>>>(
        edge, batch, w_rel0, w_root0, w_rel1, w_root1, w_rel2, w_root2,
        (uint16_t*)p_bh0, (uint16_t*)p_bl0, (uint16_t*)p_bh1, (uint16_t*)p_bl1,
        (uint16_t*)p_bh2, (uint16_t*)p_bl2);

    // layer-0 GEMM (independent of CSR build)
    k_hgemm<2, false><<<gblk, 256, smem_stage>>>(x, nullptr,
                                                 (const uint16_t*)p_bh0, (const uint16_t*)p_bl0, b_rel0);

    // CSR build
    k_hist<<<1024, 256>>>(edge, E);
    k_scan1<<<NSCAN_BLK, 1024>>>();
    k_scan2<<<1, 128>>>(NSCAN_BLK, E);
    k_scan3<<<NSCAN_BLK, 1024>>>();
    k_scatter<<<1024, 256>>>(edge, E);

    // layer 0 aggregate, then layers 1 & 2
    k_agg<true, false><<<ablk, 256>>>();
    k_hgemm<1, true><<<gblk, 256, smem_stage>>>(nullptr, (const uint32_t*)p_hh,
                                                (const uint16_t*)p_bh1, (const uint16_t*)p_bl1, b_rel1);
    k_agg<true, false><<<ablk, 256>>>();
    k_hgemm<1, true><<<gblk, 256, smem_stage>>>(nullptr, (const uint32_t*)p_hh,
                                                (const uint16_t*)p_bh2, (const uint16_t*)p_bl2, b_rel2);
    k_agg<false, true><<<ablk, 256>>>();

    // pooling + head
    k_pool<<<(N_NODES / 32 * 32 + 255) / 256, 256>>>(batch);
    k_head<<<1, 64>>>(head_w1, head_b1, head_w2, head_b2, out);
}

// round 15
// speedup vs baseline: 1.7641x; 1.0633x over previous
#include <cuda_runtime.h>
#include <cuda_bf16.h>
#include <cuda_fp16.h>
#include <cstdint>

#define N_NODES 100000
#define N_GRAPHS 64
#define HID 64
#define MAX_E 1600000
#define NSCAN_BLK 98    // ceil(100000/1024)
#define INIT_BLK 391    // ceil(100000/256)
#define BSPLIT_ELEMS (128 * 128 + 2 * 128 * 64)
#define BSPLIT_BLK ((BSPLIT_ELEMS + 255) / 256)

// ---------------- scratch (static device globals; no runtime alloc) --------
__device__ int   g_deg[N_NODES];
__device__ int   g_rowptr[N_NODES + 1];
__device__ int   g_tmp[N_NODES];
__device__ int   g_col[MAX_E];
__device__ uint32_t g_y16[N_NODES * 32];       // y in fp16 (half2 packed) — gather table
__device__ float g_r[N_NODES * HID];
__device__ float g_h[N_NODES * HID];
__device__ uint32_t g_hh[N_NODES * HID / 2];   // h bf16 (bf16x2 packed) — GEMM A input
__device__ uint16_t g_bh0[128 * 128], g_bl0[128 * 128];
__device__ uint16_t g_bh1[128 * 64],  g_bl1[128 * 64];
__device__ uint16_t g_bh2[128 * 64],  g_bl2[128 * 64];
__device__ int   g_bsum[256];
__device__ int   g_boff[256];
__device__ float g_pool[N_GRAPHS * HID];
__device__ float g_cnt[N_GRAPHS];
__device__ int   g_flags[2];

// ================= helpers ==================================================
__device__ __forceinline__ uint32_t smem_u32(const void* p) {
    uint32_t a;
    asm("{ .reg .u64 t; cvta.to.shared.u64 t, %1; cvt.u32.u64 %0, t; }" : "=r"(a) : "l"(p));
    return a;
}
__device__ __forceinline__ void ldmx4(uint32_t& r0, uint32_t& r1, uint32_t& r2, uint32_t& r3,
                                      uint32_t addr) {
    asm volatile("ldmatrix.sync.aligned.m8n8.x4.shared.b16 {%0,%1,%2,%3}, [%4];"
                 : "=r"(r0), "=r"(r1), "=r"(r2), "=r"(r3) : "r"(addr));
}
__device__ __forceinline__ void mma16816(float* c, const uint32_t* a, uint32_t b0, uint32_t b1) {
    asm volatile("mma.sync.aligned.m16n8k16.row.col.f32.bf16.bf16.f32 "
                 "{%0,%1,%2,%3}, {%4,%5,%6,%7}, {%8,%9}, {%0,%1,%2,%3};"
                 : "+f"(c[0]), "+f"(c[1]), "+f"(c[2]), "+f"(c[3])
                 : "r"(a[0]), "r"(a[1]), "r"(a[2]), "r"(a[3]), "r"(b0), "r"(b1));
}
__device__ __forceinline__ uint32_t pack_bf16x2(float x, float y) {
    __nv_bfloat162 h2 = make_bfloat162(__float2bfloat16(x), __float2bfloat16(y));
    return *(uint32_t*)&h2;
}

// ---------------- pre: init + detect + weight splits (one launch) -----------
__global__ void k_pre(const int* __restrict__ edge, const int* __restrict__ batch,
                      const float* __restrict__ Wrel0, const float* __restrict__ Wroot0,
                      const float* __restrict__ Wrel1, const float* __restrict__ Wroot1,
                      const float* __restrict__ Wrel2, const float* __restrict__ Wroot2,
                      uint16_t* __restrict__ bh0, uint16_t* __restrict__ bl0,
                      uint16_t* __restrict__ bh1, uint16_t* __restrict__ bl1,
                      uint16_t* __restrict__ bh2, uint16_t* __restrict__ bl2) {
    if (blockIdx.x < INIT_BLK) {
        int i = blockIdx.x * blockDim.x + threadIdx.x;
        if (i < N_NODES) g_deg[i] = 0;
        if (i < N_GRAPHS * HID) g_pool[i] = 0.f;
        if (i < N_GRAPHS) g_cnt[i] = 0.f;
        if (blockIdx.x < 2) {
            __shared__ int s_nz;
            int t = threadIdx.x;
            if (t == 0) s_nz = 0;
            __syncthreads();
            int v;
            if (blockIdx.x == 0) v = edge[2 * t + 1];
            else                 v = batch[2 * (30000 + t * 64) + 1];
            if (v != 0) atomicOr(&s_nz, 1);
            __syncthreads();
            if (t == 0) g_flags[blockIdx.x] = (s_nz == 0) ? 1 : 0;
        }
        return;
    }
    int idx = (blockIdx.x - INIT_BLK) * blockDim.x + threadIdx.x;
    const float* Wrel; const float* Wroot; uint16_t* bh; uint16_t* bl; int KD;
    if (idx < 128 * 128) {
        Wrel = Wrel0; Wroot = Wroot0; bh = bh0; bl = bl0; KD = 128;
    } else if (idx < 128 * 128 + 128 * 64) {
        idx -= 128 * 128;
        Wrel = Wrel1; Wroot = Wroot1; bh = bh1; bl = bl1; KD = 64;
    } else if (idx < 128 * 128 + 2 * 128 * 64) {
        idx -= 128 * 128 + 128 * 64;
        Wrel = Wrel2; Wroot = Wroot2; bh = bh2; bl = bl2; KD = 64;
    } else return;
    int k = idx >> 7, n = idx & 127;
    float v = (n < 64) ? Wrel[k * 64 + n] : Wroot[k * 64 + (n - 64)];
    __nv_bfloat16 h = __float2bfloat16(v);
    __nv_bfloat16 l = __float2bfloat16(v - __bfloat162float(h));
    bh[n * KD + k] = *(uint16_t*)&h;
    bl[n * KD + k] = *(uint16_t*)&l;
}

// ---------------- CSR build -------------------------------------------------
__global__ void k_hist(const int* __restrict__ edge, int E) {
    int f = g_flags[0];
    int stride = gridDim.x * blockDim.x;
    for (int e = blockIdx.x * blockDim.x + threadIdx.x; e < E; e += stride) {
        int d = f ? edge[2 * (E + e)] : edge[E + e];
        atomicAdd(&g_deg[d], 1);
    }
}
__global__ void k_scan1() {
    __shared__ int sm[1024];
    int i = blockIdx.x * 1024 + threadIdx.x;
    int v = (i < N_NODES) ? g_deg[i] : 0;
    sm[threadIdx.x] = v;
    __syncthreads();
    for (int off = 1; off < 1024; off <<= 1) {
        int u = (threadIdx.x >= off) ? sm[threadIdx.x - off] : 0;
        __syncthreads();
        sm[threadIdx.x] += u;
        __syncthreads();
    }
    if (i < N_NODES) g_tmp[i] = sm[threadIdx.x];
    if (threadIdx.x == 1023) g_bsum[blockIdx.x] = sm[1023];
}
__global__ void k_scan2(int nb, int E) {
    __shared__ int sm[128];
    int t = threadIdx.x;
    int v = (t < nb) ? g_bsum[t] : 0;
    sm[t] = v;
    __syncthreads();
    for (int off = 1; off < 128; off <<= 1) {
        int u = (t >= off) ? sm[t - off] : 0;
        __syncthreads();
        sm[t] += u;
        __syncthreads();
    }
    if (t < nb) g_boff[t] = sm[t] - v;
    if (t == 0) { g_rowptr[0] = 0; g_rowptr[N_NODES] = E; }
}
__global__ void k_scan3() {
    int i = blockIdx.x * 1024 + threadIdx.x;
    if (i < N_NODES) {
        int incl = g_tmp[i] + g_boff[blockIdx.x];
        g_rowptr[i + 1] = incl;
        g_tmp[i] = incl - g_deg[i];
    }
}
__global__ void k_scatter(const int* __restrict__ edge, int E) {
    int f = g_flags[0];
    int stride = gridDim.x * blockDim.x;
    for (int e = blockIdx.x * blockDim.x + threadIdx.x; e < E; e += stride) {
        int s = f ? edge[2 * e] : edge[e];
        int d = f ? edge[2 * (E + e)] : edge[E + e];
        int pos = atomicAdd(&g_tmp[d], 1);
        g_col[pos] = s;
    }
}

// =============== tensor-core fused GEMM: y = A@Wrel ; r = A@Wroot + b =======
// A single-bf16, B split hi/lo: acc = Ah*Bh + Ah*Bl (fp32, mma.sync m16n8k16).
template <int CHUNKS, bool BF16A>
__global__ __launch_bounds__(256) void k_hgemm(const float* __restrict__ A,
                                               const uint32_t* __restrict__ Abf,
                                               const uint16_t* __restrict__ Bh,
                                               const uint16_t* __restrict__ Bl,
                                               const float* __restrict__ bias) {
    extern __shared__ char smem[];
    constexpr int KD = CHUNKS * 64;                  // logical K
    constexpr int SA = 64 + 8;                       // padded stage row stride (bf16)
    constexpr int ABYTES = 64 * SA * 2;
    constexpr int BBYTES = 128 * SA * 2;
    char* a_hi = smem;
    char* b_hi = smem + ABYTES;
    char* b_lo = smem + ABYTES + BBYTES;
    float* bsh = (float*)(smem + ABYTES + 2 * BBYTES);

    const int t = threadIdx.x;
    const int wid = t >> 5;
    const int lane = t & 31;
    const int row0 = blockIdx.x * 64;

    if (t < 64) bsh[t] = bias[t];

    const int m_base = (wid & 1) * 32;
    const int n_base = (wid >> 1) * 32;

    float c[8][4];
#pragma unroll
    for (int f = 0; f < 8; f++)
#pragma unroll
        for (int i = 0; i < 4; i++) c[f][i] = 0.f;

    const uint32_t sa_hi = smem_u32(a_hi);
    const uint32_t sb_hi = smem_u32(b_hi), sb_lo = smem_u32(b_lo);

    const int a_row = (lane & 15);
    const int a_kof = (lane >> 4) * 8;
    const int b_row = ((lane >> 4) & 1) * 8 + (lane & 7);
    const int b_kof = ((lane >> 3) & 1) * 8;

#pragma unroll
    for (int chunk = 0; chunk < CHUNKS; chunk++) {
        if (chunk > 0) __syncthreads();   // smem stage reuse barrier

        // ---- A stage: 64 rows x 64 k-cols (single bf16) ----
        if (BF16A) {
            for (int g = t; g < 64 * 8; g += 256) {
                int row = g >> 3;
                int j = g & 7;
                uint4 vh = make_uint4(0, 0, 0, 0);
                if (row0 + row < N_NODES)
                    vh = ((const uint4*)Abf)[(size_t)(row0 + row) * 8 + j];
                *(uint4*)(a_hi + (uint32_t)(row * SA + j * 8) * 2) = vh;
            }
        } else {
            for (int g = t; g < 64 * 16; g += 256) {
                int row = g >> 4;
                int k4 = (g & 15) * 4;
                float4 v = make_float4(0.f, 0.f, 0.f, 0.f);
                if (row0 + row < N_NODES)
                    v = *(const float4*)(A + (size_t)(row0 + row) * KD + chunk * 64 + k4);
                uint32_t h01 = pack_bf16x2(v.x, v.y);
                uint32_t h23 = pack_bf16x2(v.z, v.w);
                *(uint2*)(a_hi + (uint32_t)(row * SA + k4) * 2) = make_uint2(h01, h23);
            }
        }
        // ---- B stage: 128 n-rows x 64 k-cols (coalesced copy of pre-split) --
        {
            for (int g = t; g < 128 * 8; g += 256) {
                int n = g >> 3;
                int j = g & 7;
                size_t gi = (size_t)n * (KD / 8) + chunk * 8 + j;
                uint32_t off = (uint32_t)(n * SA + j * 8) * 2;
                *(uint4*)(b_hi + off) = ((const uint4*)Bh)[gi];
                *(uint4*)(b_lo + off) = ((const uint4*)Bl)[gi];
            }
        }
        __syncthreads();

#pragma unroll
        for (int ks = 0; ks < 64; ks += 16) {
            uint32_t ah[2][4];
#pragma unroll
            for (int mi = 0; mi < 2; mi++) {
                uint32_t off = (uint32_t)((m_base + mi * 16 + a_row) * SA + ks + a_kof) * 2;
                ldmx4(ah[mi][0], ah[mi][1], ah[mi][2], ah[mi][3], sa_hi + off);
            }
            uint32_t bh[4][2], bl[4][2];
#pragma unroll
            for (int nj = 0; nj < 2; nj++) {
                uint32_t off = (uint32_t)((n_base + nj * 16 + b_row) * SA + ks + b_kof) * 2;
                uint32_t r0, r1, r2, r3;
                ldmx4(r0, r1, r2, r3, sb_hi + off);
                bh[nj * 2][0] = r0; bh[nj * 2][1] = r1;
                bh[nj * 2 + 1][0] = r2; bh[nj * 2 + 1][1] = r3;
                ldmx4(r0, r1, r2, r3, sb_lo + off);
                bl[nj * 2][0] = r0; bl[nj * 2][1] = r1;
                bl[nj * 2 + 1][0] = r2; bl[nj * 2 + 1][1] = r3;
            }
#pragma unroll
            for (int mi = 0; mi < 2; mi++)
#pragma unroll
                for (int ni = 0; ni < 4; ni++) {
                    float* cf = c[mi * 4 + ni];
                    mma16816(cf, ah[mi], bh[ni][0], bh[ni][1]);
                    mma16816(cf, ah[mi], bl[ni][0], bl[ni][1]);
                }
        }
    }

    // ---- epilogue: y -> fp16 half2, r -> fp32 + bias ----
    const int er = lane >> 2;
    const int ec = (lane & 3) * 2;
#pragma unroll
    for (int mi = 0; mi < 2; mi++) {
#pragma unroll
        for (int half = 0; half < 2; half++) {
            int m = m_base + mi * 16 + half * 8 + er;
            int node = row0 + m;
            if (node >= N_NODES) continue;
#pragma unroll
            for (int ni = 0; ni < 4; ni++) {
                int j = n_base + ni * 8 + ec;
                float v0 = c[mi * 4 + ni][half * 2 + 0];
                float v1 = c[mi * 4 + ni][half * 2 + 1];
                if (j < 64) {
                    __half2 p = __floats2half2_rn(v0, v1);
                    g_y16[(size_t)node * 32 + (j >> 1)] = *(uint32_t*)&p;
                } else {
                    *(float2*)(g_r + (size_t)node * 64 + (j - 64)) =
                        make_float2(v0 + bsh[j - 64], v1 + bsh[j - 63]);
                }
            }
        }
    }
}

// ---------------- aggregation: h = relu(sum_{s->i} y[s] + r[i]) -------------
template <bool EMIT_BF16, bool EMIT_F32>
__global__ void k_agg() {
    int w = (blockIdx.x * blockDim.x + threadIdx.x) >> 5;
    if (w >= N_NODES) return;                 // uniform per warp
    const int lane = threadIdx.x & 31;
    const int half = lane >> 4;               // which edge of the pair
    const int kk = lane & 15;                 // 4-channel group
    const int beg = g_rowptr[w];
    const int end = g_rowptr[w + 1];
    const uint2* y2 = (const uint2*)g_y16;    // 16 uint2 per node row

    float4 a0 = make_float4(0.f, 0.f, 0.f, 0.f);
    float4 a1 = make_float4(0.f, 0.f, 0.f, 0.f);
    int e = beg;
    for (; e + 3 < end; e += 4) {
        int s0 = __ldg(&g_col[e + half]);
        int s1 = __ldg(&g_col[e + 2 + half]);
        uint2 u0 = __ldg(&y2[(size_t)s0 * 16 + kk]);
        uint2 u1 = __ldg(&y2[(size_t)s1 * 16 + kk]);
        float2 f00 = __half22float2(*(__half2*)&u0.x);
        float2 f01 = __half22float2(*(__half2*)&u0.y);
        float2 f10 = __half22float2(*(__half2*)&u1.x);
        float2 f11 = __half22float2(*(__half2*)&u1.y);
        a0.x += f00.x; a0.y += f00.y; a0.z += f01.x; a0.w += f01.y;
        a1.x += f10.x; a1.y += f10.y; a1.z += f11.x; a1.w += f11.y;
    }
    while (e < end) {                         // uniform loop, predicated load
        if (e + half < end) {
            int s = __ldg(&g_col[e + half]);
            uint2 u = __ldg(&y2[(size_t)s * 16 + kk]);
            float2 f0 = __half22float2(*(__half2*)&u.x);
            float2 f1 = __half22float2(*(__half2*)&u.y);
            a0.x += f0.x; a0.y += f0.y; a0.z += f1.x; a0.w += f1.y;
        }
        e += 2;
    }
    a0.x += a1.x; a0.y += a1.y; a0.z += a1.z; a0.w += a1.w;
    a0.x += __shfl_xor_sync(0xffffffffu, a0.x, 16);
    a0.y += __shfl_xor_sync(0xffffffffu, a0.y, 16);
    a0.z += __shfl_xor_sync(0xffffffffu, a0.z, 16);
    a0.w += __shfl_xor_sync(0xffffffffu, a0.w, 16);

    if (lane < 16) {
        float4 rv = __ldg(&((const float4*)g_r)[(size_t)w * 16 + kk]);
        float4 o;
        o.x = fmaxf(a0.x + rv.x, 0.f);
        o.y = fmaxf(a0.y + rv.y, 0.f);
        o.z = fmaxf(a0.z + rv.z, 0.f);
        o.w = fmaxf(a0.w + rv.w, 0.f);
        if (EMIT_F32)
            ((float4*)g_h)[(size_t)w * 16 + kk] = o;
        if (EMIT_BF16)
            *(uint2*)&g_hh[(size_t)w * 32 + 2 * kk] =
                make_uint2(pack_bf16x2(o.x, o.y), pack_bf16x2(o.z, o.w));
    }
}

// ---------------- pooling ---------------------------------------------------
__global__ void k_pool(const int* __restrict__ batch) {
    int chunk = (blockIdx.x * blockDim.x + threadIdx.x) >> 5;
    int lane = threadIdx.x & 31;
    int n0 = chunk * 32;
    if (n0 >= N_NODES) return;
    int n1 = min(n0 + 32, N_NODES);
    int f = g_flags[1];
    const float2* h2 = (const float2*)g_h;
    float2 acc = make_float2(0.f, 0.f);
    int cnt = 0;
    int cur = f ? batch[2 * n0] : batch[n0];
    for (int n = n0; n < n1; n++) {
        int g = f ? batch[2 * n] : batch[n];
        if (g != cur) {
            atomicAdd(&g_pool[cur * 64 + 2 * lane], acc.x);
            atomicAdd(&g_pool[cur * 64 + 2 * lane + 1], acc.y);
            if (lane == 0) atomicAdd(&g_cnt[cur], (float)cnt);
            acc = make_float2(0.f, 0.f); cnt = 0; cur = g;
        }
        float2 v = h2[(size_t)n * 32 + lane];
        acc.x += v.x; acc.y += v.y; cnt++;
    }
    atomicAdd(&g_pool[cur * 64 + 2 * lane], acc.x);
    atomicAdd(&g_pool[cur * 64 + 2 * lane + 1], acc.y);
    if (lane == 0) atomicAdd(&g_cnt[cur], (float)cnt);
}

// ---------------- head ------------------------------------------------------
__global__ void k_head(const float* __restrict__ w1, const float* __restrict__ b1,
                       const float* __restrict__ w2, const float* __restrict__ b2,
                       float* __restrict__ out) {
    __shared__ float s_w1[64 * 64], s_b1[64], s_w2[128], s_b2[2];
    int t = threadIdx.x;
    for (int i = t; i < 64 * 64; i += 64) s_w1[i] = w1[i];
    s_b1[t] = b1[t];
    for (int i = t; i < 128; i += 64) s_w2[i] = w2[i];
    if (t < 2) s_b2[t] = b2[t];
    __syncthreads();

    float cnt = fmaxf(g_cnt[t], 1.f);
    float m[64];
#pragma unroll
    for (int c = 0; c < 64; c++) m[c] = g_pool[t * 64 + c] / cnt;

    float o0 = s_b2[0], o1 = s_b2[1];
    for (int j = 0; j < 64; j++) {
        float z = s_b1[j];
#pragma unroll 8
        for (int k = 0; k < 64; k++) z += m[k] * s_w1[k * 64 + j];
        z = fmaxf(z, 0.f);
        o0 += z * s_w2[j * 2];
        o1 += z * s_w2[j * 2 + 1];
    }
    out[t * 2 + 0] = o0;
    out[t * 2 + 1] = o1;
}

// ---------------- launch ----------------------------------------------------
extern "C" void kernel_launch(void* const* d_in, const int* in_sizes, int n_in,
                              void* d_out, int out_size) {
    const float* x       = (const float*)d_in[0];
    const int*   edge    = (const int*)d_in[1];
    const int*   batch   = (const int*)d_in[2];
    const float* w_rel0  = (const float*)d_in[3];
    const float* b_rel0  = (const float*)d_in[4];
    const float* w_root0 = (const float*)d_in[5];
    const float* w_rel1  = (const float*)d_in[6];
    const float* b_rel1  = (const float*)d_in[7];
    const float* w_root1 = (const float*)d_in[8];
    const float* w_rel2  = (const float*)d_in[9];
    const float* b_rel2  = (const float*)d_in[10];
    const float* w_root2 = (const float*)d_in[11];
    const float* head_w1 = (const float*)d_in[12];
    const float* head_b1 = (const float*)d_in[13];
    const float* head_w2 = (const float*)d_in[14];
    const float* head_b2 = (const float*)d_in[15];
    float* out = (float*)d_out;

    const int E = in_sizes[1] / 2;

    // one-time stream/event objects (host-side resources; no device allocs)
    static cudaStream_t s_aux = nullptr;
    static cudaEvent_t ev_fork = nullptr, ev_join = nullptr;
    if (s_aux == nullptr) {
        cudaStreamCreateWithFlags(&s_aux, cudaStreamNonBlocking);
        cudaEventCreateWithFlags(&ev_fork, cudaEventDisableTiming);
        cudaEventCreateWithFlags(&ev_join, cudaEventDisableTiming);
    }

    // stage smem: A(64x72) + 2*B(128x72) bf16 + bias
    const int smem_stage = (64 * 72 * 2) + 2 * (128 * 72 * 2) + 256;   // 46336
    cudaFuncSetAttribute((const void*)k_hgemm<2, false>,
                         cudaFuncAttributeMaxDynamicSharedMemorySize, smem_stage);
    cudaFuncSetAttribute((const void*)k_hgemm<1, true>,
                         cudaFuncAttributeMaxDynamicSharedMemorySize, smem_stage);

    void *p_hh, *p_bh0, *p_bl0, *p_bh1, *p_bl1, *p_bh2, *p_bl2;
    cudaGetSymbolAddress(&p_hh, g_hh);
    cudaGetSymbolAddress(&p_bh0, g_bh0);
    cudaGetSymbolAddress(&p_bl0, g_bl0);
    cudaGetSymbolAddress(&p_bh1, g_bh1);
    cudaGetSymbolAddress(&p_bl1, g_bl1);
    cudaGetSymbolAddress(&p_bh2, g_bh2);
    cudaGetSymbolAddress(&p_bl2, g_bl2);

    const int gblk = (N_NODES + 63) / 64;   // 1563
    const int ablk = (N_NODES + 7) / 8;

    // pre: init + detect + weight splits (one launch, main stream)
    k_pre<<<INIT_BLK + BSPLIT_BLK, 256>>>(
        edge, batch, w_rel0, w_root0, w_rel1, w_root1, w_rel2, w_root2,
        (uint16_t*)p_bh0, (uint16_t*)p_bl0, (uint16_t*)p_bh1, (uint16_t*)p_bl1,
        (uint16_t*)p_bh2, (uint16_t*)p_bl2);

    // ---- fork: gemm0 runs concurrently with the CSR build ----
    cudaEventRecord(ev_fork, 0);
    cudaStreamWaitEvent(s_aux, ev_fork, 0);

    // branch A (aux stream): layer-0 GEMM
    k_hgemm<2, false><<<gblk, 256, smem_stage, s_aux>>>(x, nullptr,
        (const uint16_t*)p_bh0, (const uint16_t*)p_bl0, b_rel0);

    // branch B (main stream): CSR build
    k_hist<<<1024, 256>>>(edge, E);
    k_scan1<<<NSCAN_BLK, 1024>>>();
    k_scan2<<<1, 128>>>(NSCAN_BLK, E);
    k_scan3<<<NSCAN_BLK, 1024>>>();
    k_scatter<<<1024, 256>>>(edge, E);

    // ---- join ----
    cudaEventRecord(ev_join, s_aux);
    cudaStreamWaitEvent(0, ev_join, 0);

    // layer 0 aggregate, then layers 1 & 2
    k_agg<true, false><<<ablk, 256>>>();
    k_hgemm<1, true><<<gblk, 256, smem_stage>>>(nullptr, (const uint32_t*)p_hh,
                                                (const uint16_t*)p_bh1, (const uint16_t*)p_bl1, b_rel1);
    k_agg<true, false><<<ablk, 256>>>();
    k_hgemm<1, true><<<gblk, 256, smem_stage>>>(nullptr, (const uint32_t*)p_hh,
                                                (const uint16_t*)p_bh2, (const uint16_t*)p_bl2, b_rel2);
    k_agg<false, true><<<ablk, 256>>>();

    // pooling + head
    k_pool<<<(N_NODES / 32 * 32 + 255) / 256, 256>>>(batch);
    k_head<<<1, 64>>>(head_w1, head_b1, head_w2, head_b2, out);
}